// round 12
// baseline (speedup 1.0000x reference)
#include <cuda_runtime.h>
#include <cuda_fp16.h>
#include <math.h>
#include <stdint.h>

#define B 2
#define L 2048
#define DIMM 1024
#define H 16
#define DH 64
#define BH (B*H)      // 32
#define TOK (B*L)     // 4096

// ---------------- scratch ----------------
__device__ __half g_qkh[BH*L*DH];
__device__ __half g_vh [BH*L*DH];
__device__ float g_dot[BH*L];
__device__ float g_norm2[BH*L];
__device__ unsigned int g_maxn2[BH];
__device__ unsigned char g_hq[BH*L];
__device__ unsigned char g_hk[BH*L];
__device__ __half g_XH [TOK*DIMM];
__device__ __half g_XL [TOK*DIMM];
__device__ __half g_WqH[DIMM*DIMM];
__device__ __half g_WqL[DIMM*DIMM];
__device__ __half g_WvH[DIMM*DIMM];

__device__ __forceinline__ uint32_t f22h2(float a, float b){
    __half2 h = __floats2half2_rn(a, b);
    return *(uint32_t*)&h;
}
__device__ __forceinline__ float ex2f(float x){
    float r; asm("ex2.approx.f32 %0, %1;" : "=f"(r) : "f"(x)); return r;
}
__device__ __forceinline__ void mma_f16(float c[4],
    uint32_t a0, uint32_t a1, uint32_t a2, uint32_t a3,
    uint32_t b0, uint32_t b1)
{
    asm("mma.sync.aligned.m16n8k16.row.col.f32.f16.f16.f32 "
        "{%0,%1,%2,%3}, {%4,%5,%6,%7}, {%8,%9}, {%0,%1,%2,%3};"
        : "+f"(c[0]), "+f"(c[1]), "+f"(c[2]), "+f"(c[3])
        : "r"(a0), "r"(a1), "r"(a2), "r"(a3), "r"(b0), "r"(b1));
}

// ============ split conversion ============
__global__ __launch_bounds__(256)
void cvt_kernel(const float* __restrict__ src, __half* __restrict__ dh,
                __half* __restrict__ dl, int n4, int makeLo)
{
    int i = blockIdx.x*blockDim.x + threadIdx.x;
    if (blockIdx.x == 0 && threadIdx.x < BH) g_maxn2[threadIdx.x] = 0u;
    if (i >= n4) return;
    float4 v = ((const float4*)src)[i];
    __half2 h0 = __floats2half2_rn(v.x, v.y);
    __half2 h1 = __floats2half2_rn(v.z, v.w);
    ((__half2*)dh)[2*i]   = h0;
    ((__half2*)dh)[2*i+1] = h1;
    if (makeLo) {
        __half2 l0 = __floats2half2_rn((v.x - __low2float(h0))*2048.0f,
                                       (v.y - __high2float(h0))*2048.0f);
        __half2 l1 = __floats2half2_rn((v.z - __low2float(h1))*2048.0f,
                                       (v.w - __high2float(h1))*2048.0f);
        ((__half2*)dl)[2*i]   = l0;
        ((__half2*)dl)[2*i+1] = l1;
    }
}

// ============ fp16 projection: 4 warps, 32 rows/warp (B-frag reuse x2) ============
#define HPSTR 72
#define PH_XH 0
#define PH_WH (128*HPSTR)
#define PH_XL (PH_WH + 64*HPSTR)
#define PH_WL (PH_XL + 128*HPSTR)
#define PROJ_SM_BYTES ((PH_WL + 64*HPSTR)*2)   // 55296

__global__ __launch_bounds__(128)
void proj_h_kernel(const float* __restrict__ bq,
                   const float* __restrict__ bv,
                   const float* __restrict__ ha)
{
    extern __shared__ __half hsm[];
    __half* XH = hsm + PH_XH;
    __half* WH = hsm + PH_WH;
    __half* XL = hsm + PH_XL;
    __half* WL = hsm + PH_WL;

    const bool SPLIT = (blockIdx.z == 0);
    __half* out = SPLIT ? g_qkh : g_vh;
    const __half* WHg = SPLIT ? g_WqH : g_WvH;
    const float* bias = SPLIT ? bq : bv;

    const int m0 = blockIdx.y * 128;
    const int n0 = blockIdx.x * 64;
    const int tid = threadIdx.x;
    const int warp = tid >> 5;
    const int lane = tid & 31;
    const int gy = lane >> 2;
    const int gx = lane & 3;
    const int qr = warp * 32;            // warp owns rows [qr, qr+32)

    // fill coords
    const int xr = tid;                  // X: one row per thread (0..127)
    const int wr = tid >> 1;             // W: 0..63
    const int wc = (tid & 1) * 16;       // halves

    float acc1[2][8][4];
    float acc2[2][8][4];
    #pragma unroll
    for (int t=0;t<2;t++)
        #pragma unroll
        for (int nt=0;nt<8;nt++)
            #pragma unroll
            for (int c=0;c<4;c++){ acc1[t][nt][c] = 0.0f; acc2[t][nt][c] = 0.0f; }

    const __half* xhp = &g_XH[(size_t)(m0+xr)*DIMM];
    const __half* xlp = &g_XL[(size_t)(m0+xr)*DIMM];
    const __half* whp = &WHg  [(size_t)(n0+wr)*DIMM + wc];
    const __half* wlp = &g_WqL[(size_t)(n0+wr)*DIMM + wc];

    for (int kk = 0; kk < DIMM; kk += 32) {
        // prefetch gmem chunks into regs
        uint4 xh[4], xl[4], wh[2], wl[2];
        #pragma unroll
        for (int j=0;j<4;j++) xh[j] = *(const uint4*)&xhp[kk + j*8];
        #pragma unroll
        for (int j=0;j<2;j++) wh[j] = *(const uint4*)&whp[kk + j*8];
        if (SPLIT) {
            #pragma unroll
            for (int j=0;j<4;j++) xl[j] = *(const uint4*)&xlp[kk + j*8];
            #pragma unroll
            for (int j=0;j<2;j++) wl[j] = *(const uint4*)&wlp[kk + j*8];
        }

        __syncthreads();
        #pragma unroll
        for (int j=0;j<4;j++) *(uint4*)&XH[xr*HPSTR + j*8] = xh[j];
        #pragma unroll
        for (int j=0;j<2;j++) *(uint4*)&WH[wr*HPSTR + wc + j*8] = wh[j];
        if (SPLIT) {
            #pragma unroll
            for (int j=0;j<4;j++) *(uint4*)&XL[xr*HPSTR + j*8] = xl[j];
            #pragma unroll
            for (int j=0;j<2;j++) *(uint4*)&WL[wr*HPSTR + wc + j*8] = wl[j];
        }
        __syncthreads();

        #pragma unroll
        for (int ks = 0; ks < 2; ks++) {
            uint32_t ah[2][4], al[2][4];
            #pragma unroll
            for (int t = 0; t < 2; t++) {
                int r0 = qr + t*16 + gy;
                ah[t][0] = *(uint32_t*)&XH[(r0  )*HPSTR + ks*16 + 2*gx];
                ah[t][1] = *(uint32_t*)&XH[(r0+8)*HPSTR + ks*16 + 2*gx];
                ah[t][2] = *(uint32_t*)&XH[(r0  )*HPSTR + ks*16 + 2*gx + 8];
                ah[t][3] = *(uint32_t*)&XH[(r0+8)*HPSTR + ks*16 + 2*gx + 8];
                if (SPLIT) {
                    al[t][0] = *(uint32_t*)&XL[(r0  )*HPSTR + ks*16 + 2*gx];
                    al[t][1] = *(uint32_t*)&XL[(r0+8)*HPSTR + ks*16 + 2*gx];
                    al[t][2] = *(uint32_t*)&XL[(r0  )*HPSTR + ks*16 + 2*gx + 8];
                    al[t][3] = *(uint32_t*)&XL[(r0+8)*HPSTR + ks*16 + 2*gx + 8];
                }
            }
            #pragma unroll
            for (int nt = 0; nt < 8; nt++) {
                uint32_t bh0 = *(uint32_t*)&WH[(nt*8+gy)*HPSTR + ks*16 + 2*gx];
                uint32_t bh1 = *(uint32_t*)&WH[(nt*8+gy)*HPSTR + ks*16 + 2*gx + 8];
                uint32_t bl0 = 0, bl1 = 0;
                if (SPLIT) {
                    bl0 = *(uint32_t*)&WL[(nt*8+gy)*HPSTR + ks*16 + 2*gx];
                    bl1 = *(uint32_t*)&WL[(nt*8+gy)*HPSTR + ks*16 + 2*gx + 8];
                }
                #pragma unroll
                for (int t = 0; t < 2; t++) {
                    mma_f16(acc1[t][nt], ah[t][0], ah[t][1], ah[t][2], ah[t][3], bh0, bh1);
                    if (SPLIT) {
                        mma_f16(acc2[t][nt], ah[t][0], ah[t][1], ah[t][2], ah[t][3], bl0, bl1);
                        mma_f16(acc2[t][nt], al[t][0], al[t][1], al[t][2], al[t][3], bh0, bh1);
                    }
                }
            }
        }
    }

    // ---- epilogue: bias, fp16 store, fused hash stage-1 (qk only) ----
    const int hh = blockIdx.x;
    const float inv2048 = 1.0f/2048.0f;
    #pragma unroll
    for (int t = 0; t < 2; t++) {
        const int m_0 = m0 + qr + t*16 + gy;
        const int m_1 = m_0 + 8;
        const int b0_ = m_0 >> 11, l0_ = m_0 & (L-1);
        const int b1_ = m_1 >> 11, l1_ = m_1 & (L-1);
        __half* o0 = &out[(((size_t)(b0_*H + hh)*L + l0_)*DH)];
        __half* o1 = &out[(((size_t)(b1_*H + hh)*L + l1_)*DH)];

        float dot0 = 0.f, n20 = 0.f, dot1 = 0.f, n21 = 0.f;
        #pragma unroll
        for (int nt = 0; nt < 8; nt++) {
            float bs0 = bias[hh*64 + nt*8 + 2*gx];
            float bs1 = bias[hh*64 + nt*8 + 2*gx + 1];
            float v00, v01, v10, v11;
            if (SPLIT) {
                v00 = fmaf(acc2[t][nt][0], inv2048, acc1[t][nt][0]) + bs0;
                v01 = fmaf(acc2[t][nt][1], inv2048, acc1[t][nt][1]) + bs1;
                v10 = fmaf(acc2[t][nt][2], inv2048, acc1[t][nt][2]) + bs0;
                v11 = fmaf(acc2[t][nt][3], inv2048, acc1[t][nt][3]) + bs1;
            } else {
                v00 = acc1[t][nt][0] + bs0; v01 = acc1[t][nt][1] + bs1;
                v10 = acc1[t][nt][2] + bs0; v11 = acc1[t][nt][3] + bs1;
            }
            *(uint32_t*)&o0[nt*8 + 2*gx] = f22h2(v00, v01);
            *(uint32_t*)&o1[nt*8 + 2*gx] = f22h2(v10, v11);
            if (SPLIT) {
                float a0 = ha[nt*8 + 2*gx], a1 = ha[nt*8 + 2*gx + 1];
                dot0 = fmaf(v00, a0, fmaf(v01, a1, dot0));
                dot1 = fmaf(v10, a0, fmaf(v11, a1, dot1));
                n20  = fmaf(v00, v00, fmaf(v01, v01, n20));
                n21  = fmaf(v10, v10, fmaf(v11, v11, n21));
            }
        }
        if (SPLIT) {
            #pragma unroll
            for (int o = 1; o <= 2; o <<= 1) {
                dot0 += __shfl_xor_sync(0xffffffffu, dot0, o);
                dot1 += __shfl_xor_sync(0xffffffffu, dot1, o);
                n20  += __shfl_xor_sync(0xffffffffu, n20, o);
                n21  += __shfl_xor_sync(0xffffffffu, n21, o);
            }
            if (gx == 0) {
                size_t gw0 = (size_t)(b0_*H + hh)*L + l0_;
                size_t gw1 = (size_t)(b1_*H + hh)*L + l1_;
                g_dot[gw0] = dot0; g_norm2[gw0] = n20;
                g_dot[gw1] = dot1; g_norm2[gw1] = n21;
                atomicMax(&g_maxn2[b0_*H + hh], __float_as_uint(n20));
                atomicMax(&g_maxn2[b1_*H + hh], __float_as_uint(n21));
            }
        }
    }
}

// ---------------- hash ----------------
__global__ void hash2_kernel(const float* __restrict__ ha) {
    int t = blockIdx.x * blockDim.x + threadIdx.x;
    if (t >= BH*L) return;
    float dot = g_dot[t], n2 = g_norm2[t];
    float maxn = sqrtf(__uint_as_float(g_maxn2[t >> 11]));
    float s = 0.75f / fmaxf(maxn, 1e-12f);
    float nk2 = s*s*n2;
    float hkval = s*dot + (0.5f - nk2)*ha[DH] + (0.5f - nk2*nk2)*ha[DH+1];
    g_hq[t] = (dot   >= 0.0f) ? 1 : 0;
    g_hk[t] = (hkval >= 0.0f) ? 1 : 0;
}

// ============ fp16 flash attention: P in registers, base-2 softmax ============
#define HSTR 72
#define QS_OFF 0
#define KS_OFF (128*HSTR)
#define VT_OFF (KS_OFF + 64*HSTR)
#define HK_OFF (VT_OFF + 64*HSTR)
#define ASM_HALVES (HK_OFF + 128)
#define ASM_BYTES (ASM_HALVES*2)

#define C_SCL 0.1803368801111713f
#define C_NEG 14426.950408889634f

__global__ __launch_bounds__(256, 2)
void attn_kernel(float* __restrict__ out) {
    extern __shared__ __half smh[];
    __half* Qs = smh + QS_OFF;
    __half* Ks = smh + KS_OFF;
    __half* Vt = smh + VT_OFF;
    float* hkf = (float*)(smh + HK_OFF);

    const int bh = blockIdx.y;
    const int q0 = blockIdx.x * 128;
    const int tid = threadIdx.x;
    const int warp = tid >> 5;
    const int lane = tid & 31;
    const int gy = lane >> 2;
    const int gx = lane & 3;
    const int qr = warp * 16;

    {
        int r = tid >> 1, c0 = (tid & 1) * 32;
        const __half* qp = &g_qkh[((size_t)bh*L + q0 + r)*DH + c0];
        #pragma unroll
        for (int c8 = 0; c8 < 4; c8++)
            *(uint4*)&Qs[r*HSTR + c0 + c8*8] = *(const uint4*)&qp[c8*8];
    }

    const float fq0 = (float)g_hq[(size_t)bh*L + q0 + qr + gy];
    const float fq1 = (float)g_hq[(size_t)bh*L + q0 + qr + gy + 8];

    float O[8][4];
    #pragma unroll
    for (int nt=0;nt<8;nt++)
        #pragma unroll
        for (int c=0;c<4;c++) O[nt][c] = 0.0f;
    float m0 = -INFINITY, m1 = -INFINITY, l0 = 0.0f, l1 = 0.0f;

    const int fr = tid >> 2;
    const int fc = (tid & 3) * 16;
    const int vd0 = warp * 8;

    for (int k0 = 0; k0 < L; k0 += 64) {
        uint4 kA, kB;
        {
            const __half* kp = &g_qkh[((size_t)bh*L + k0 + fr)*DH + fc];
            kA = ((const uint4*)kp)[0];
            kB = ((const uint4*)kp)[1];
        }
        uint4 va, vb;
        {
            const __half* vp = &g_vh[((size_t)bh*L + k0 + 2*lane)*DH + vd0];
            va = *(const uint4*)vp;
            vb = *(const uint4*)(vp + DH);
        }
        unsigned char hkb = 0;
        if (tid < 64) hkb = g_hk[(size_t)bh*L + k0 + tid];

        __syncthreads();
        *(uint4*)&Ks[fr*HSTR + fc]     = kA;
        *(uint4*)&Ks[fr*HSTR + fc + 8] = kB;
        {
            const uint32_t* aw = (const uint32_t*)&va;
            const uint32_t* bw = (const uint32_t*)&vb;
            #pragma unroll
            for (int j=0;j<4;j++){
                uint32_t lo = __byte_perm(aw[j], bw[j], 0x5410);
                uint32_t hi = __byte_perm(aw[j], bw[j], 0x7632);
                *(uint32_t*)&Vt[(vd0+2*j  )*HSTR + 2*lane] = lo;
                *(uint32_t*)&Vt[(vd0+2*j+1)*HSTR + 2*lane] = hi;
            }
        }
        if (tid < 64) hkf[tid] = (float)hkb;
        __syncthreads();

        float S[8][4];
        #pragma unroll
        for (int nt=0;nt<8;nt++)
            #pragma unroll
            for (int c=0;c<4;c++) S[nt][c] = 0.0f;

        #pragma unroll
        for (int ks = 0; ks < 4; ks++) {
            uint32_t a0 = *(uint32_t*)&Qs[(qr+gy  )*HSTR + ks*16 + 2*gx];
            uint32_t a1 = *(uint32_t*)&Qs[(qr+gy+8)*HSTR + ks*16 + 2*gx];
            uint32_t a2 = *(uint32_t*)&Qs[(qr+gy  )*HSTR + ks*16 + 2*gx + 8];
            uint32_t a3 = *(uint32_t*)&Qs[(qr+gy+8)*HSTR + ks*16 + 2*gx + 8];
            #pragma unroll
            for (int nt = 0; nt < 8; nt++) {
                uint32_t b0 = *(uint32_t*)&Ks[(nt*8+gy)*HSTR + ks*16 + 2*gx];
                uint32_t b1 = *(uint32_t*)&Ks[(nt*8+gy)*HSTR + ks*16 + 2*gx + 8];
                mma_f16(S[nt], a0, a1, a2, a3, b0, b1);
            }
        }

        float mx0 = -INFINITY, mx1 = -INFINITY;
        #pragma unroll
        for (int nt = 0; nt < 8; nt++) {
            float fk0 = hkf[nt*8 + 2*gx];
            float fk1 = hkf[nt*8 + 2*gx + 1];
            S[nt][0] = fmaf(S[nt][0], C_SCL, -C_NEG*fabsf(fq0 - fk0));
            S[nt][1] = fmaf(S[nt][1], C_SCL, -C_NEG*fabsf(fq0 - fk1));
            S[nt][2] = fmaf(S[nt][2], C_SCL, -C_NEG*fabsf(fq1 - fk0));
            S[nt][3] = fmaf(S[nt][3], C_SCL, -C_NEG*fabsf(fq1 - fk1));
            mx0 = fmaxf(mx0, fmaxf(S[nt][0], S[nt][1]));
            mx1 = fmaxf(mx1, fmaxf(S[nt][2], S[nt][3]));
        }
        #pragma unroll
        for (int o = 1; o <= 2; o <<= 1) {
            mx0 = fmaxf(mx0, __shfl_xor_sync(0xffffffffu, mx0, o));
            mx1 = fmaxf(mx1, __shfl_xor_sync(0xffffffffu, mx1, o));
        }
        float mn0 = fmaxf(m0, mx0), mn1 = fmaxf(m1, mx1);
        float cr0 = ex2f(m0 - mn0), cr1 = ex2f(m1 - mn1);
        m0 = mn0; m1 = mn1;

        uint32_t ph0[8], ph1[8];
        float s0 = 0.0f, s1 = 0.0f;
        #pragma unroll
        for (int nt = 0; nt < 8; nt++) {
            float p0 = ex2f(S[nt][0] - mn0);
            float p1 = ex2f(S[nt][1] - mn0);
            float p2 = ex2f(S[nt][2] - mn1);
            float p3 = ex2f(S[nt][3] - mn1);
            s0 += p0 + p1; s1 += p2 + p3;
            ph0[nt] = f22h2(p0, p1);
            ph1[nt] = f22h2(p2, p3);
        }
        #pragma unroll
        for (int o = 1; o <= 2; o <<= 1) {
            s0 += __shfl_xor_sync(0xffffffffu, s0, o);
            s1 += __shfl_xor_sync(0xffffffffu, s1, o);
        }
        l0 = l0*cr0 + s0;
        l1 = l1*cr1 + s1;

        #pragma unroll
        for (int nt = 0; nt < 8; nt++) {
            O[nt][0] *= cr0; O[nt][1] *= cr0;
            O[nt][2] *= cr1; O[nt][3] *= cr1;
        }

        #pragma unroll
        for (int ks = 0; ks < 4; ks++) {
            uint32_t a0 = ph0[2*ks];
            uint32_t a1 = ph1[2*ks];
            uint32_t a2 = ph0[2*ks+1];
            uint32_t a3 = ph1[2*ks+1];
            #pragma unroll
            for (int nt = 0; nt < 8; nt++) {
                uint32_t b0 = *(uint32_t*)&Vt[(nt*8+gy)*HSTR + ks*16 + 2*gx];
                uint32_t b1 = *(uint32_t*)&Vt[(nt*8+gy)*HSTR + ks*16 + 2*gx + 8];
                mma_f16(O[nt], a0, a1, a2, a3, b0, b1);
            }
        }
    }

    const int bb = bh >> 4, hh = bh & 15;
    const float inv0 = 1.0f / l0, inv1 = 1.0f / l1;
    const int l_0 = q0 + qr + gy, l_1 = l_0 + 8;
    float* o0 = &out[((size_t)bb*L + l_0)*DIMM + hh*DH];
    float* o1 = &out[((size_t)bb*L + l_1)*DIMM + hh*DH];
    #pragma unroll
    for (int nt = 0; nt < 8; nt++) {
        *(float2*)&o0[nt*8 + 2*gx] = make_float2(O[nt][0]*inv0, O[nt][1]*inv0);
        *(float2*)&o1[nt*8 + 2*gx] = make_float2(O[nt][2]*inv1, O[nt][3]*inv1);
    }
}

// ---------------- launch ----------------
extern "C" void kernel_launch(void* const* d_in, const int* in_sizes, int n_in,
                              void* d_out, int out_size) {
    const float* X  = (const float*)d_in[0];
    const float* Wq = (const float*)d_in[1];
    const float* bq = (const float*)d_in[2];
    const float* Wv = (const float*)d_in[3];
    const float* bv = (const float*)d_in[4];
    const float* ha = (const float*)d_in[5];
    float* out = (float*)d_out;

    cudaFuncSetAttribute(proj_h_kernel, cudaFuncAttributeMaxDynamicSharedMemorySize, PROJ_SM_BYTES);
    cudaFuncSetAttribute(attn_kernel,   cudaFuncAttributeMaxDynamicSharedMemorySize, ASM_BYTES);

    __half *xh, *xl, *wqh, *wql, *wvh;
    cudaGetSymbolAddress((void**)&xh,  g_XH);
    cudaGetSymbolAddress((void**)&xl,  g_XL);
    cudaGetSymbolAddress((void**)&wqh, g_WqH);
    cudaGetSymbolAddress((void**)&wql, g_WqL);
    cudaGetSymbolAddress((void**)&wvh, g_WvH);
    cvt_kernel<<<(TOK*DIMM/4)/256, 256>>>(X,  xh,  xl,  TOK*DIMM/4, 1);
    cvt_kernel<<<(DIMM*DIMM/4)/256, 256>>>(Wq, wqh, wql, DIMM*DIMM/4, 1);
    cvt_kernel<<<(DIMM*DIMM/4)/256, 256>>>(Wv, wvh, wvh, DIMM*DIMM/4, 0);

    dim3 pg(DIMM/64, TOK/128, 2);
    proj_h_kernel<<<pg, 128, PROJ_SM_BYTES>>>(bq, bv, ha);

    hash2_kernel<<<(BH*L)/256, 256>>>(ha);

    dim3 ag(L/128, BH);
    attn_kernel<<<ag, 256, ASM_BYTES>>>(out);
}

// round 13
// speedup vs baseline: 1.0610x; 1.0610x over previous
#include <cuda_runtime.h>
#include <cuda_fp16.h>
#include <math.h>
#include <stdint.h>

#define B 2
#define L 2048
#define DIMM 1024
#define H 16
#define DH 64
#define BH (B*H)      // 32
#define TOK (B*L)     // 4096

// ---------------- scratch ----------------
__device__ __half g_qkh[BH*L*DH];
__device__ __half g_vh [BH*L*DH];
__device__ float g_dot[BH*L];
__device__ float g_norm2[BH*L];
__device__ unsigned int g_maxn2[BH];
__device__ unsigned char g_hq[BH*L];
__device__ unsigned char g_hk[BH*L];
__device__ __half g_XH [TOK*DIMM];
__device__ __half g_XL [TOK*DIMM];
__device__ __half g_WqH[DIMM*DIMM];
__device__ __half g_WqL[DIMM*DIMM];
__device__ __half g_WvH[DIMM*DIMM];

__device__ __forceinline__ uint32_t f22h2(float a, float b){
    __half2 h = __floats2half2_rn(a, b);
    return *(uint32_t*)&h;
}
__device__ __forceinline__ float ex2f(float x){
    float r; asm("ex2.approx.f32 %0, %1;" : "=f"(r) : "f"(x)); return r;
}
__device__ __forceinline__ void mma_f16(float c[4],
    uint32_t a0, uint32_t a1, uint32_t a2, uint32_t a3,
    uint32_t b0, uint32_t b1)
{
    asm("mma.sync.aligned.m16n8k16.row.col.f32.f16.f16.f32 "
        "{%0,%1,%2,%3}, {%4,%5,%6,%7}, {%8,%9}, {%0,%1,%2,%3};"
        : "+f"(c[0]), "+f"(c[1]), "+f"(c[2]), "+f"(c[3])
        : "r"(a0), "r"(a1), "r"(a2), "r"(a3), "r"(b0), "r"(b1));
}

// ============ split conversion ============
__global__ __launch_bounds__(256)
void cvt_kernel(const float* __restrict__ src, __half* __restrict__ dh,
                __half* __restrict__ dl, int n4, int makeLo)
{
    int i = blockIdx.x*blockDim.x + threadIdx.x;
    if (blockIdx.x == 0 && threadIdx.x < BH) g_maxn2[threadIdx.x] = 0u;
    if (i >= n4) return;
    float4 v = ((const float4*)src)[i];
    __half2 h0 = __floats2half2_rn(v.x, v.y);
    __half2 h1 = __floats2half2_rn(v.z, v.w);
    ((__half2*)dh)[2*i]   = h0;
    ((__half2*)dh)[2*i+1] = h1;
    if (makeLo) {
        __half2 l0 = __floats2half2_rn((v.x - __low2float(h0))*2048.0f,
                                       (v.y - __high2float(h0))*2048.0f);
        __half2 l1 = __floats2half2_rn((v.z - __low2float(h1))*2048.0f,
                                       (v.w - __high2float(h1))*2048.0f);
        ((__half2*)dl)[2*i]   = l0;
        ((__half2*)dl)[2*i+1] = l1;
    }
}

// ============ fp16 projection: 8 warps in 4x2 grid, 32x32 per warp ============
#define HPSTR 72
#define PH_XH 0
#define PH_WH (128*HPSTR)
#define PH_XL (PH_WH + 64*HPSTR)
#define PH_WL (PH_XL + 128*HPSTR)
#define PROJ_SM_BYTES ((PH_WL + 64*HPSTR)*2)   // 55296

__global__ __launch_bounds__(256, 2)
void proj_h_kernel(const float* __restrict__ bq,
                   const float* __restrict__ bv,
                   const float* __restrict__ ha)
{
    extern __shared__ __half hsm[];
    __half* XH = hsm + PH_XH;
    __half* WH = hsm + PH_WH;
    __half* XL = hsm + PH_XL;
    __half* WL = hsm + PH_WL;

    const bool SPLIT = (blockIdx.z == 0);
    __half* out = SPLIT ? g_qkh : g_vh;
    const __half* WHg = SPLIT ? g_WqH : g_WvH;
    const float* bias = SPLIT ? bq : bv;

    const int m0 = blockIdx.y * 128;
    const int n0 = blockIdx.x * 64;
    const int tid = threadIdx.x;
    const int warp = tid >> 5;
    const int lane = tid & 31;
    const int gy = lane >> 2;
    const int gx = lane & 3;
    const int wm = warp >> 1;            // 0..3 : m-group
    const int wn = warp & 1;             // 0..1 : n-group
    const int qr = wm * 32;              // warp rows [qr, qr+32)
    const int nb = wn * 32;              // warp cols [nb, nb+32)

    const int fxr = tid >> 1;
    const int fxc = (tid & 1) * 16;
    const int fwr = tid >> 2;
    const int fwc = (tid & 3) * 8;

    float acc1[2][4][4];
    float acc2[2][4][4];
    #pragma unroll
    for (int t=0;t<2;t++)
        #pragma unroll
        for (int nt=0;nt<4;nt++)
            #pragma unroll
            for (int c=0;c<4;c++){ acc1[t][nt][c] = 0.0f; acc2[t][nt][c] = 0.0f; }

    const __half* xhp = &g_XH[(size_t)(m0+fxr)*DIMM + fxc];
    const __half* xlp = &g_XL[(size_t)(m0+fxr)*DIMM + fxc];
    const __half* whp = &WHg  [(size_t)(n0+fwr)*DIMM + fwc];
    const __half* wlp = &g_WqL[(size_t)(n0+fwr)*DIMM + fwc];

    for (int kk = 0; kk < DIMM; kk += 32) {
        uint4 xh0 = *(const uint4*)&xhp[kk];
        uint4 xh1 = *(const uint4*)&xhp[kk+8];
        uint4 wh  = *(const uint4*)&whp[kk];
        uint4 xl0, xl1, wl;
        if (SPLIT) {
            xl0 = *(const uint4*)&xlp[kk];
            xl1 = *(const uint4*)&xlp[kk+8];
            wl  = *(const uint4*)&wlp[kk];
        }

        __syncthreads();
        *(uint4*)&XH[fxr*HPSTR + fxc]     = xh0;
        *(uint4*)&XH[fxr*HPSTR + fxc + 8] = xh1;
        *(uint4*)&WH[fwr*HPSTR + fwc]     = wh;
        if (SPLIT) {
            *(uint4*)&XL[fxr*HPSTR + fxc]     = xl0;
            *(uint4*)&XL[fxr*HPSTR + fxc + 8] = xl1;
            *(uint4*)&WL[fwr*HPSTR + fwc]     = wl;
        }
        __syncthreads();

        #pragma unroll
        for (int ks = 0; ks < 2; ks++) {
            uint32_t ah[2][4], al[2][4];
            #pragma unroll
            for (int t = 0; t < 2; t++) {
                int r0 = qr + t*16 + gy;
                ah[t][0] = *(uint32_t*)&XH[(r0  )*HPSTR + ks*16 + 2*gx];
                ah[t][1] = *(uint32_t*)&XH[(r0+8)*HPSTR + ks*16 + 2*gx];
                ah[t][2] = *(uint32_t*)&XH[(r0  )*HPSTR + ks*16 + 2*gx + 8];
                ah[t][3] = *(uint32_t*)&XH[(r0+8)*HPSTR + ks*16 + 2*gx + 8];
                if (SPLIT) {
                    al[t][0] = *(uint32_t*)&XL[(r0  )*HPSTR + ks*16 + 2*gx];
                    al[t][1] = *(uint32_t*)&XL[(r0+8)*HPSTR + ks*16 + 2*gx];
                    al[t][2] = *(uint32_t*)&XL[(r0  )*HPSTR + ks*16 + 2*gx + 8];
                    al[t][3] = *(uint32_t*)&XL[(r0+8)*HPSTR + ks*16 + 2*gx + 8];
                }
            }
            #pragma unroll
            for (int nt = 0; nt < 4; nt++) {
                int brow = nb + nt*8 + gy;
                uint32_t bh0 = *(uint32_t*)&WH[brow*HPSTR + ks*16 + 2*gx];
                uint32_t bh1 = *(uint32_t*)&WH[brow*HPSTR + ks*16 + 2*gx + 8];
                uint32_t bl0 = 0, bl1 = 0;
                if (SPLIT) {
                    bl0 = *(uint32_t*)&WL[brow*HPSTR + ks*16 + 2*gx];
                    bl1 = *(uint32_t*)&WL[brow*HPSTR + ks*16 + 2*gx + 8];
                }
                #pragma unroll
                for (int t = 0; t < 2; t++) {
                    mma_f16(acc1[t][nt], ah[t][0], ah[t][1], ah[t][2], ah[t][3], bh0, bh1);
                    if (SPLIT) {
                        mma_f16(acc2[t][nt], ah[t][0], ah[t][1], ah[t][2], ah[t][3], bl0, bl1);
                        mma_f16(acc2[t][nt], al[t][0], al[t][1], al[t][2], al[t][3], bh0, bh1);
                    }
                }
            }
        }
    }

    // ---- epilogue: bias, fp16 store, hash partials ----
    const int hh = blockIdx.x;
    const float inv2048 = 1.0f/2048.0f;
    float* pd = (float*)hsm;          // [128][2] dot partials
    float* pn = pd + 256;             // [128][2] norm2 partials
    __syncthreads();                   // smem tiles no longer needed

    #pragma unroll
    for (int t = 0; t < 2; t++) {
        const int r_0 = qr + t*16 + gy;        // local rows
        const int r_1 = r_0 + 8;
        const int m_0 = m0 + r_0, m_1 = m0 + r_1;
        const int b0_ = m_0 >> 11, l0_ = m_0 & (L-1);
        const int b1_ = m_1 >> 11, l1_ = m_1 & (L-1);
        __half* o0 = &out[(((size_t)(b0_*H + hh)*L + l0_)*DH)];
        __half* o1 = &out[(((size_t)(b1_*H + hh)*L + l1_)*DH)];

        float dot0 = 0.f, n20 = 0.f, dot1 = 0.f, n21 = 0.f;
        #pragma unroll
        for (int nt = 0; nt < 4; nt++) {
            int col = nb + nt*8 + 2*gx;
            float bs0 = bias[hh*64 + col];
            float bs1 = bias[hh*64 + col + 1];
            float v00, v01, v10, v11;
            if (SPLIT) {
                v00 = fmaf(acc2[t][nt][0], inv2048, acc1[t][nt][0]) + bs0;
                v01 = fmaf(acc2[t][nt][1], inv2048, acc1[t][nt][1]) + bs1;
                v10 = fmaf(acc2[t][nt][2], inv2048, acc1[t][nt][2]) + bs0;
                v11 = fmaf(acc2[t][nt][3], inv2048, acc1[t][nt][3]) + bs1;
            } else {
                v00 = acc1[t][nt][0] + bs0; v01 = acc1[t][nt][1] + bs1;
                v10 = acc1[t][nt][2] + bs0; v11 = acc1[t][nt][3] + bs1;
            }
            *(uint32_t*)&o0[col] = f22h2(v00, v01);
            *(uint32_t*)&o1[col] = f22h2(v10, v11);
            if (SPLIT) {
                float a0 = ha[col], a1 = ha[col + 1];
                dot0 = fmaf(v00, a0, fmaf(v01, a1, dot0));
                dot1 = fmaf(v10, a0, fmaf(v11, a1, dot1));
                n20  = fmaf(v00, v00, fmaf(v01, v01, n20));
                n21  = fmaf(v10, v10, fmaf(v11, v11, n21));
            }
        }
        if (SPLIT) {
            #pragma unroll
            for (int o = 1; o <= 2; o <<= 1) {
                dot0 += __shfl_xor_sync(0xffffffffu, dot0, o);
                dot1 += __shfl_xor_sync(0xffffffffu, dot1, o);
                n20  += __shfl_xor_sync(0xffffffffu, n20, o);
                n21  += __shfl_xor_sync(0xffffffffu, n21, o);
            }
            if (gx == 0) {
                pd[r_0*2 + wn] = dot0;  pn[r_0*2 + wn] = n20;
                pd[r_1*2 + wn] = dot1;  pn[r_1*2 + wn] = n21;
            }
        }
    }
    if (SPLIT) {
        __syncthreads();
        if (tid < 128) {
            int r = tid;
            float dot = pd[r*2] + pd[r*2+1];
            float n2  = pn[r*2] + pn[r*2+1];
            int m = m0 + r;
            int bb = m >> 11, ll = m & (L-1);
            size_t gw = (size_t)(bb*H + hh)*L + ll;
            g_dot[gw] = dot;
            g_norm2[gw] = n2;
            atomicMax(&g_maxn2[bb*H + hh], __float_as_uint(n2));
        }
    }
}

// ---------------- hash ----------------
__global__ void hash2_kernel(const float* __restrict__ ha) {
    int t = blockIdx.x * blockDim.x + threadIdx.x;
    if (t >= BH*L) return;
    float dot = g_dot[t], n2 = g_norm2[t];
    float maxn = sqrtf(__uint_as_float(g_maxn2[t >> 11]));
    float s = 0.75f / fmaxf(maxn, 1e-12f);
    float nk2 = s*s*n2;
    float hkval = s*dot + (0.5f - nk2)*ha[DH] + (0.5f - nk2*nk2)*ha[DH+1];
    g_hq[t] = (dot   >= 0.0f) ? 1 : 0;
    g_hk[t] = (hkval >= 0.0f) ? 1 : 0;
}

// ============ fp16 flash attention (unchanged from R10) ============
#define HSTR 72
#define QS_OFF 0
#define KS_OFF (128*HSTR)
#define VT_OFF (KS_OFF + 64*HSTR)
#define HK_OFF (VT_OFF + 64*HSTR)
#define ASM_HALVES (HK_OFF + 128)
#define ASM_BYTES (ASM_HALVES*2)

#define C_SCL 0.1803368801111713f
#define C_NEG 14426.950408889634f

__global__ __launch_bounds__(256, 2)
void attn_kernel(float* __restrict__ out) {
    extern __shared__ __half smh[];
    __half* Qs = smh + QS_OFF;
    __half* Ks = smh + KS_OFF;
    __half* Vt = smh + VT_OFF;
    float* hkf = (float*)(smh + HK_OFF);

    const int bh = blockIdx.y;
    const int q0 = blockIdx.x * 128;
    const int tid = threadIdx.x;
    const int warp = tid >> 5;
    const int lane = tid & 31;
    const int gy = lane >> 2;
    const int gx = lane & 3;
    const int qr = warp * 16;

    {
        int r = tid >> 1, c0 = (tid & 1) * 32;
        const __half* qp = &g_qkh[((size_t)bh*L + q0 + r)*DH + c0];
        #pragma unroll
        for (int c8 = 0; c8 < 4; c8++)
            *(uint4*)&Qs[r*HSTR + c0 + c8*8] = *(const uint4*)&qp[c8*8];
    }

    const float fq0 = (float)g_hq[(size_t)bh*L + q0 + qr + gy];
    const float fq1 = (float)g_hq[(size_t)bh*L + q0 + qr + gy + 8];

    float O[8][4];
    #pragma unroll
    for (int nt=0;nt<8;nt++)
        #pragma unroll
        for (int c=0;c<4;c++) O[nt][c] = 0.0f;
    float m0 = -INFINITY, m1 = -INFINITY, l0 = 0.0f, l1 = 0.0f;

    const int fr = tid >> 2;
    const int fc = (tid & 3) * 16;
    const int vd0 = warp * 8;

    for (int k0 = 0; k0 < L; k0 += 64) {
        uint4 kA, kB;
        {
            const __half* kp = &g_qkh[((size_t)bh*L + k0 + fr)*DH + fc];
            kA = ((const uint4*)kp)[0];
            kB = ((const uint4*)kp)[1];
        }
        uint4 va, vb;
        {
            const __half* vp = &g_vh[((size_t)bh*L + k0 + 2*lane)*DH + vd0];
            va = *(const uint4*)vp;
            vb = *(const uint4*)(vp + DH);
        }
        unsigned char hkb = 0;
        if (tid < 64) hkb = g_hk[(size_t)bh*L + k0 + tid];

        __syncthreads();
        *(uint4*)&Ks[fr*HSTR + fc]     = kA;
        *(uint4*)&Ks[fr*HSTR + fc + 8] = kB;
        {
            const uint32_t* aw = (const uint32_t*)&va;
            const uint32_t* bw = (const uint32_t*)&vb;
            #pragma unroll
            for (int j=0;j<4;j++){
                uint32_t lo = __byte_perm(aw[j], bw[j], 0x5410);
                uint32_t hi = __byte_perm(aw[j], bw[j], 0x7632);
                *(uint32_t*)&Vt[(vd0+2*j  )*HSTR + 2*lane] = lo;
                *(uint32_t*)&Vt[(vd0+2*j+1)*HSTR + 2*lane] = hi;
            }
        }
        if (tid < 64) hkf[tid] = (float)hkb;
        __syncthreads();

        float S[8][4];
        #pragma unroll
        for (int nt=0;nt<8;nt++)
            #pragma unroll
            for (int c=0;c<4;c++) S[nt][c] = 0.0f;

        #pragma unroll
        for (int ks = 0; ks < 4; ks++) {
            uint32_t a0 = *(uint32_t*)&Qs[(qr+gy  )*HSTR + ks*16 + 2*gx];
            uint32_t a1 = *(uint32_t*)&Qs[(qr+gy+8)*HSTR + ks*16 + 2*gx];
            uint32_t a2 = *(uint32_t*)&Qs[(qr+gy  )*HSTR + ks*16 + 2*gx + 8];
            uint32_t a3 = *(uint32_t*)&Qs[(qr+gy+8)*HSTR + ks*16 + 2*gx + 8];
            #pragma unroll
            for (int nt = 0; nt < 8; nt++) {
                uint32_t b0 = *(uint32_t*)&Ks[(nt*8+gy)*HSTR + ks*16 + 2*gx];
                uint32_t b1 = *(uint32_t*)&Ks[(nt*8+gy)*HSTR + ks*16 + 2*gx + 8];
                mma_f16(S[nt], a0, a1, a2, a3, b0, b1);
            }
        }

        float mx0 = -INFINITY, mx1 = -INFINITY;
        #pragma unroll
        for (int nt = 0; nt < 8; nt++) {
            float fk0 = hkf[nt*8 + 2*gx];
            float fk1 = hkf[nt*8 + 2*gx + 1];
            S[nt][0] = fmaf(S[nt][0], C_SCL, -C_NEG*fabsf(fq0 - fk0));
            S[nt][1] = fmaf(S[nt][1], C_SCL, -C_NEG*fabsf(fq0 - fk1));
            S[nt][2] = fmaf(S[nt][2], C_SCL, -C_NEG*fabsf(fq1 - fk0));
            S[nt][3] = fmaf(S[nt][3], C_SCL, -C_NEG*fabsf(fq1 - fk1));
            mx0 = fmaxf(mx0, fmaxf(S[nt][0], S[nt][1]));
            mx1 = fmaxf(mx1, fmaxf(S[nt][2], S[nt][3]));
        }
        #pragma unroll
        for (int o = 1; o <= 2; o <<= 1) {
            mx0 = fmaxf(mx0, __shfl_xor_sync(0xffffffffu, mx0, o));
            mx1 = fmaxf(mx1, __shfl_xor_sync(0xffffffffu, mx1, o));
        }
        float mn0 = fmaxf(m0, mx0), mn1 = fmaxf(m1, mx1);
        float cr0 = ex2f(m0 - mn0), cr1 = ex2f(m1 - mn1);
        m0 = mn0; m1 = mn1;

        uint32_t ph0[8], ph1[8];
        float s0 = 0.0f, s1 = 0.0f;
        #pragma unroll
        for (int nt = 0; nt < 8; nt++) {
            float p0 = ex2f(S[nt][0] - mn0);
            float p1 = ex2f(S[nt][1] - mn0);
            float p2 = ex2f(S[nt][2] - mn1);
            float p3 = ex2f(S[nt][3] - mn1);
            s0 += p0 + p1; s1 += p2 + p3;
            ph0[nt] = f22h2(p0, p1);
            ph1[nt] = f22h2(p2, p3);
        }
        #pragma unroll
        for (int o = 1; o <= 2; o <<= 1) {
            s0 += __shfl_xor_sync(0xffffffffu, s0, o);
            s1 += __shfl_xor_sync(0xffffffffu, s1, o);
        }
        l0 = l0*cr0 + s0;
        l1 = l1*cr1 + s1;

        #pragma unroll
        for (int nt = 0; nt < 8; nt++) {
            O[nt][0] *= cr0; O[nt][1] *= cr0;
            O[nt][2] *= cr1; O[nt][3] *= cr1;
        }

        #pragma unroll
        for (int ks = 0; ks < 4; ks++) {
            uint32_t a0 = ph0[2*ks];
            uint32_t a1 = ph1[2*ks];
            uint32_t a2 = ph0[2*ks+1];
            uint32_t a3 = ph1[2*ks+1];
            #pragma unroll
            for (int nt = 0; nt < 8; nt++) {
                uint32_t b0 = *(uint32_t*)&Vt[(nt*8+gy)*HSTR + ks*16 + 2*gx];
                uint32_t b1 = *(uint32_t*)&Vt[(nt*8+gy)*HSTR + ks*16 + 2*gx + 8];
                mma_f16(O[nt], a0, a1, a2, a3, b0, b1);
            }
        }
    }

    const int bb = bh >> 4, hh = bh & 15;
    const float inv0 = 1.0f / l0, inv1 = 1.0f / l1;
    const int l_0 = q0 + qr + gy, l_1 = l_0 + 8;
    float* o0 = &out[((size_t)bb*L + l_0)*DIMM + hh*DH];
    float* o1 = &out[((size_t)bb*L + l_1)*DIMM + hh*DH];
    #pragma unroll
    for (int nt = 0; nt < 8; nt++) {
        *(float2*)&o0[nt*8 + 2*gx] = make_float2(O[nt][0]*inv0, O[nt][1]*inv0);
        *(float2*)&o1[nt*8 + 2*gx] = make_float2(O[nt][2]*inv1, O[nt][3]*inv1);
    }
}

// ---------------- launch ----------------
extern "C" void kernel_launch(void* const* d_in, const int* in_sizes, int n_in,
                              void* d_out, int out_size) {
    const float* X  = (const float*)d_in[0];
    const float* Wq = (const float*)d_in[1];
    const float* bq = (const float*)d_in[2];
    const float* Wv = (const float*)d_in[3];
    const float* bv = (const float*)d_in[4];
    const float* ha = (const float*)d_in[5];
    float* out = (float*)d_out;

    cudaFuncSetAttribute(proj_h_kernel, cudaFuncAttributeMaxDynamicSharedMemorySize, PROJ_SM_BYTES);
    cudaFuncSetAttribute(attn_kernel,   cudaFuncAttributeMaxDynamicSharedMemorySize, ASM_BYTES);

    __half *xh, *xl, *wqh, *wql, *wvh;
    cudaGetSymbolAddress((void**)&xh,  g_XH);
    cudaGetSymbolAddress((void**)&xl,  g_XL);
    cudaGetSymbolAddress((void**)&wqh, g_WqH);
    cudaGetSymbolAddress((void**)&wql, g_WqL);
    cudaGetSymbolAddress((void**)&wvh, g_WvH);
    cvt_kernel<<<(TOK*DIMM/4)/256, 256>>>(X,  xh,  xl,  TOK*DIMM/4, 1);
    cvt_kernel<<<(DIMM*DIMM/4)/256, 256>>>(Wq, wqh, wql, DIMM*DIMM/4, 1);
    cvt_kernel<<<(DIMM*DIMM/4)/256, 256>>>(Wv, wvh, wvh, DIMM*DIMM/4, 0);

    dim3 pg(DIMM/64, TOK/128, 2);
    proj_h_kernel<<<pg, 256, PROJ_SM_BYTES>>>(bq, bv, ha);

    hash2_kernel<<<(BH*L)/256, 256>>>(ha);

    dim3 ag(L/128, BH);
    attn_kernel<<<ag, 256, ASM_BYTES>>>(out);
}

// round 14
// speedup vs baseline: 1.1282x; 1.0633x over previous
#include <cuda_runtime.h>
#include <cuda_fp16.h>
#include <math.h>
#include <stdint.h>

#define B 2
#define L 2048
#define DIMM 1024
#define H 16
#define DH 64
#define BH (B*H)      // 32
#define TOK (B*L)     // 4096

// ---------------- scratch ----------------
__device__ __half g_qkh[BH*L*DH];
__device__ __half g_vh [BH*L*DH];
__device__ float g_dot[BH*L];
__device__ float g_norm2[BH*L];
__device__ unsigned int g_maxn2[BH];
__device__ unsigned char g_hq[BH*L];
__device__ unsigned char g_hk[BH*L];
__device__ __half g_XH [TOK*DIMM];
__device__ __half g_XL [TOK*DIMM];
__device__ __half g_WqH[DIMM*DIMM];
__device__ __half g_WqL[DIMM*DIMM];
__device__ __half g_WvH[DIMM*DIMM];

__device__ __forceinline__ uint32_t f22h2(float a, float b){
    __half2 h = __floats2half2_rn(a, b);
    return *(uint32_t*)&h;
}
__device__ __forceinline__ float ex2f(float x){
    float r; asm("ex2.approx.f32 %0, %1;" : "=f"(r) : "f"(x)); return r;
}
__device__ __forceinline__ void mma_f16(float c[4],
    uint32_t a0, uint32_t a1, uint32_t a2, uint32_t a3,
    uint32_t b0, uint32_t b1)
{
    asm("mma.sync.aligned.m16n8k16.row.col.f32.f16.f16.f32 "
        "{%0,%1,%2,%3}, {%4,%5,%6,%7}, {%8,%9}, {%0,%1,%2,%3};"
        : "+f"(c[0]), "+f"(c[1]), "+f"(c[2]), "+f"(c[3])
        : "r"(a0), "r"(a1), "r"(a2), "r"(a3), "r"(b0), "r"(b1));
}
__device__ __forceinline__ uint32_t smem_u32(const void* p){
    uint32_t a;
    asm("{ .reg .u64 t; cvta.to.shared.u64 t, %1; cvt.u32.u64 %0, t; }" : "=r"(a) : "l"(p));
    return a;
}
#define CP16(dst, src) asm volatile("cp.async.ca.shared.global [%0], [%1], 16;" :: "r"(dst), "l"(src))
#define CP_COMMIT()    asm volatile("cp.async.commit_group;" ::: "memory")
#define CP_WAIT1()     asm volatile("cp.async.wait_group 1;" ::: "memory")

// ============ split conversion ============
__global__ __launch_bounds__(256)
void cvt_kernel(const float* __restrict__ src, __half* __restrict__ dh,
                __half* __restrict__ dl, int n4, int makeLo)
{
    int i = blockIdx.x*blockDim.x + threadIdx.x;
    if (blockIdx.x == 0 && threadIdx.x < BH) g_maxn2[threadIdx.x] = 0u;
    if (i >= n4) return;
    float4 v = ((const float4*)src)[i];
    __half2 h0 = __floats2half2_rn(v.x, v.y);
    __half2 h1 = __floats2half2_rn(v.z, v.w);
    ((__half2*)dh)[2*i]   = h0;
    ((__half2*)dh)[2*i+1] = h1;
    if (makeLo) {
        __half2 l0 = __floats2half2_rn((v.x - __low2float(h0))*2048.0f,
                                       (v.y - __high2float(h0))*2048.0f);
        __half2 l1 = __floats2half2_rn((v.z - __low2float(h1))*2048.0f,
                                       (v.w - __high2float(h1))*2048.0f);
        ((__half2*)dl)[2*i]   = l0;
        ((__half2*)dl)[2*i+1] = l1;
    }
}

// ============ fp16 projection: cp.async double-buffered, 8 warps 4x2 ============
// stage layout (halves): XH[128][40] | XL[128][40] | WH[64][40] | WL[64][40] = 15360 halves
#define HP2 40
#define ST_HALVES 15360
#define ST_BYTES  30720
#define XH_O 0
#define XL_O 10240           // bytes
#define WH_O 20480
#define WL_O 25600
#define PROJ_SM_BYTES (2*ST_BYTES)   // 61440

__global__ __launch_bounds__(256, 2)
void proj_h_kernel(const float* __restrict__ bq,
                   const float* __restrict__ bv,
                   const float* __restrict__ ha)
{
    extern __shared__ __half hsm[];
    const uint32_t sb = smem_u32(hsm);

    const bool SPLIT = (blockIdx.z == 0);
    __half* out = SPLIT ? g_qkh : g_vh;
    const __half* WHg = SPLIT ? g_WqH : g_WvH;
    const float* bias = SPLIT ? bq : bv;

    const int m0 = blockIdx.y * 128;
    const int n0 = blockIdx.x * 64;
    const int tid = threadIdx.x;
    const int warp = tid >> 5;
    const int lane = tid & 31;
    const int gy = lane >> 2;
    const int gx = lane & 3;
    const int wm = warp >> 1;            // 0..3
    const int wn = warp & 1;             // 0..1
    const int qr = wm * 32;
    const int nb = wn * 32;

    // fill coords
    const int xr = tid >> 1, xc = (tid & 1) * 16;   // X rows/halves
    const int wr = tid >> 2, wc = (tid & 3) * 8;    // W rows/halves

    const __half* xhp = &g_XH[(size_t)(m0+xr)*DIMM + xc];
    const __half* xlp = &g_XL[(size_t)(m0+xr)*DIMM + xc];
    const __half* whp = &WHg  [(size_t)(n0+wr)*DIMM + wc];
    const __half* wlp = &g_WqL[(size_t)(n0+wr)*DIMM + wc];

    const uint32_t dXH = sb + XH_O + ((uint32_t)xr*HP2 + xc)*2u;
    const uint32_t dXL = sb + XL_O + ((uint32_t)xr*HP2 + xc)*2u;
    const uint32_t dWH = sb + WH_O + ((uint32_t)wr*HP2 + wc)*2u;
    const uint32_t dWL = sb + WL_O + ((uint32_t)wr*HP2 + wc)*2u;

    float acc1[2][4][4];
    float acc2[2][4][4];
    #pragma unroll
    for (int t=0;t<2;t++)
        #pragma unroll
        for (int nt=0;nt<4;nt++)
            #pragma unroll
            for (int c=0;c<4;c++){ acc1[t][nt][c] = 0.0f; acc2[t][nt][c] = 0.0f; }

    // prologue: fill chunk 0 into stage 0
    {
        CP16(dXH,      xhp);
        CP16(dXH + 16, xhp + 8);
        CP16(dWH,      whp);
        if (SPLIT) {
            CP16(dXL,      xlp);
            CP16(dXL + 16, xlp + 8);
            CP16(dWL,      wlp);
        }
        CP_COMMIT();
    }

    for (int c = 0; c < 32; c++) {
        // issue next chunk's fill into the other stage
        if (c < 31) {
            const int kk = (c + 1) * 32;
            const uint32_t so = ((c + 1) & 1) * (uint32_t)ST_BYTES;
            CP16(dXH + so,      xhp + kk);
            CP16(dXH + so + 16, xhp + kk + 8);
            CP16(dWH + so,      whp + kk);
            if (SPLIT) {
                CP16(dXL + so,      xlp + kk);
                CP16(dXL + so + 16, xlp + kk + 8);
                CP16(dWL + so,      wlp + kk);
            }
        }
        CP_COMMIT();
        CP_WAIT1();           // chunk c's fill complete
        __syncthreads();      // visible to all warps

        const __half* XHs = hsm + (c & 1) * ST_HALVES;
        const __half* XLs = XHs + 5120;
        const __half* WHs = XHs + 10240;
        const __half* WLs = XHs + 12800;

        #pragma unroll
        for (int ks = 0; ks < 2; ks++) {
            uint32_t ah[2][4], al[2][4];
            #pragma unroll
            for (int t = 0; t < 2; t++) {
                int r0 = qr + t*16 + gy;
                ah[t][0] = *(uint32_t*)&XHs[(r0  )*HP2 + ks*16 + 2*gx];
                ah[t][1] = *(uint32_t*)&XHs[(r0+8)*HP2 + ks*16 + 2*gx];
                ah[t][2] = *(uint32_t*)&XHs[(r0  )*HP2 + ks*16 + 2*gx + 8];
                ah[t][3] = *(uint32_t*)&XHs[(r0+8)*HP2 + ks*16 + 2*gx + 8];
                if (SPLIT) {
                    al[t][0] = *(uint32_t*)&XLs[(r0  )*HP2 + ks*16 + 2*gx];
                    al[t][1] = *(uint32_t*)&XLs[(r0+8)*HP2 + ks*16 + 2*gx];
                    al[t][2] = *(uint32_t*)&XLs[(r0  )*HP2 + ks*16 + 2*gx + 8];
                    al[t][3] = *(uint32_t*)&XLs[(r0+8)*HP2 + ks*16 + 2*gx + 8];
                }
            }
            #pragma unroll
            for (int nt = 0; nt < 4; nt++) {
                int brow = nb + nt*8 + gy;
                uint32_t bh0 = *(uint32_t*)&WHs[brow*HP2 + ks*16 + 2*gx];
                uint32_t bh1 = *(uint32_t*)&WHs[brow*HP2 + ks*16 + 2*gx + 8];
                uint32_t bl0 = 0, bl1 = 0;
                if (SPLIT) {
                    bl0 = *(uint32_t*)&WLs[brow*HP2 + ks*16 + 2*gx];
                    bl1 = *(uint32_t*)&WLs[brow*HP2 + ks*16 + 2*gx + 8];
                }
                #pragma unroll
                for (int t = 0; t < 2; t++) {
                    mma_f16(acc1[t][nt], ah[t][0], ah[t][1], ah[t][2], ah[t][3], bh0, bh1);
                    if (SPLIT) {
                        mma_f16(acc2[t][nt], ah[t][0], ah[t][1], ah[t][2], ah[t][3], bl0, bl1);
                        mma_f16(acc2[t][nt], al[t][0], al[t][1], al[t][2], al[t][3], bh0, bh1);
                    }
                }
            }
        }
        __syncthreads();      // protect this stage before fill(c+2) overwrites it
    }

    // ---- epilogue: bias, fp16 store, hash partials ----
    const int hh = blockIdx.x;
    const float inv2048 = 1.0f/2048.0f;
    float* pd = (float*)hsm;
    float* pn = pd + 256;

    #pragma unroll
    for (int t = 0; t < 2; t++) {
        const int r_0 = qr + t*16 + gy;
        const int r_1 = r_0 + 8;
        const int m_0 = m0 + r_0, m_1 = m0 + r_1;
        const int b0_ = m_0 >> 11, l0_ = m_0 & (L-1);
        const int b1_ = m_1 >> 11, l1_ = m_1 & (L-1);
        __half* o0 = &out[(((size_t)(b0_*H + hh)*L + l0_)*DH)];
        __half* o1 = &out[(((size_t)(b1_*H + hh)*L + l1_)*DH)];

        float dot0 = 0.f, n20 = 0.f, dot1 = 0.f, n21 = 0.f;
        #pragma unroll
        for (int nt = 0; nt < 4; nt++) {
            int col = nb + nt*8 + 2*gx;
            float bs0 = bias[hh*64 + col];
            float bs1 = bias[hh*64 + col + 1];
            float v00, v01, v10, v11;
            if (SPLIT) {
                v00 = fmaf(acc2[t][nt][0], inv2048, acc1[t][nt][0]) + bs0;
                v01 = fmaf(acc2[t][nt][1], inv2048, acc1[t][nt][1]) + bs1;
                v10 = fmaf(acc2[t][nt][2], inv2048, acc1[t][nt][2]) + bs0;
                v11 = fmaf(acc2[t][nt][3], inv2048, acc1[t][nt][3]) + bs1;
            } else {
                v00 = acc1[t][nt][0] + bs0; v01 = acc1[t][nt][1] + bs1;
                v10 = acc1[t][nt][2] + bs0; v11 = acc1[t][nt][3] + bs1;
            }
            *(uint32_t*)&o0[col] = f22h2(v00, v01);
            *(uint32_t*)&o1[col] = f22h2(v10, v11);
            if (SPLIT) {
                float a0 = ha[col], a1 = ha[col + 1];
                dot0 = fmaf(v00, a0, fmaf(v01, a1, dot0));
                dot1 = fmaf(v10, a0, fmaf(v11, a1, dot1));
                n20  = fmaf(v00, v00, fmaf(v01, v01, n20));
                n21  = fmaf(v10, v10, fmaf(v11, v11, n21));
            }
        }
        if (SPLIT) {
            #pragma unroll
            for (int o = 1; o <= 2; o <<= 1) {
                dot0 += __shfl_xor_sync(0xffffffffu, dot0, o);
                dot1 += __shfl_xor_sync(0xffffffffu, dot1, o);
                n20  += __shfl_xor_sync(0xffffffffu, n20, o);
                n21  += __shfl_xor_sync(0xffffffffu, n21, o);
            }
            if (gx == 0) {
                pd[r_0*2 + wn] = dot0;  pn[r_0*2 + wn] = n20;
                pd[r_1*2 + wn] = dot1;  pn[r_1*2 + wn] = n21;
            }
        }
    }
    if (SPLIT) {
        __syncthreads();
        if (tid < 128) {
            int r = tid;
            float dot = pd[r*2] + pd[r*2+1];
            float n2  = pn[r*2] + pn[r*2+1];
            int m = m0 + r;
            int bb = m >> 11, ll = m & (L-1);
            size_t gw = (size_t)(bb*H + hh)*L + ll;
            g_dot[gw] = dot;
            g_norm2[gw] = n2;
            atomicMax(&g_maxn2[bb*H + hh], __float_as_uint(n2));
        }
    }
}

// ---------------- hash ----------------
__global__ void hash2_kernel(const float* __restrict__ ha) {
    int t = blockIdx.x * blockDim.x + threadIdx.x;
    if (t >= BH*L) return;
    float dot = g_dot[t], n2 = g_norm2[t];
    float maxn = sqrtf(__uint_as_float(g_maxn2[t >> 11]));
    float s = 0.75f / fmaxf(maxn, 1e-12f);
    float nk2 = s*s*n2;
    float hkval = s*dot + (0.5f - nk2)*ha[DH] + (0.5f - nk2*nk2)*ha[DH+1];
    g_hq[t] = (dot   >= 0.0f) ? 1 : 0;
    g_hk[t] = (hkval >= 0.0f) ? 1 : 0;
}

// ============ fp16 flash attention (unchanged from R10) ============
#define HSTR 72
#define QS_OFF 0
#define KS_OFF (128*HSTR)
#define VT_OFF (KS_OFF + 64*HSTR)
#define HK_OFF (VT_OFF + 64*HSTR)
#define ASM_HALVES (HK_OFF + 128)
#define ASM_BYTES (ASM_HALVES*2)

#define C_SCL 0.1803368801111713f
#define C_NEG 14426.950408889634f

__global__ __launch_bounds__(256, 2)
void attn_kernel(float* __restrict__ out) {
    extern __shared__ __half smh[];
    __half* Qs = smh + QS_OFF;
    __half* Ks = smh + KS_OFF;
    __half* Vt = smh + VT_OFF;
    float* hkf = (float*)(smh + HK_OFF);

    const int bh = blockIdx.y;
    const int q0 = blockIdx.x * 128;
    const int tid = threadIdx.x;
    const int warp = tid >> 5;
    const int lane = tid & 31;
    const int gy = lane >> 2;
    const int gx = lane & 3;
    const int qr = warp * 16;

    {
        int r = tid >> 1, c0 = (tid & 1) * 32;
        const __half* qp = &g_qkh[((size_t)bh*L + q0 + r)*DH + c0];
        #pragma unroll
        for (int c8 = 0; c8 < 4; c8++)
            *(uint4*)&Qs[r*HSTR + c0 + c8*8] = *(const uint4*)&qp[c8*8];
    }

    const float fq0 = (float)g_hq[(size_t)bh*L + q0 + qr + gy];
    const float fq1 = (float)g_hq[(size_t)bh*L + q0 + qr + gy + 8];

    float O[8][4];
    #pragma unroll
    for (int nt=0;nt<8;nt++)
        #pragma unroll
        for (int c=0;c<4;c++) O[nt][c] = 0.0f;
    float m0 = -INFINITY, m1 = -INFINITY, l0 = 0.0f, l1 = 0.0f;

    const int fr = tid >> 2;
    const int fc = (tid & 3) * 16;
    const int vd0 = warp * 8;

    for (int k0 = 0; k0 < L; k0 += 64) {
        uint4 kA, kB;
        {
            const __half* kp = &g_qkh[((size_t)bh*L + k0 + fr)*DH + fc];
            kA = ((const uint4*)kp)[0];
            kB = ((const uint4*)kp)[1];
        }
        uint4 va, vb;
        {
            const __half* vp = &g_vh[((size_t)bh*L + k0 + 2*lane)*DH + vd0];
            va = *(const uint4*)vp;
            vb = *(const uint4*)(vp + DH);
        }
        unsigned char hkb = 0;
        if (tid < 64) hkb = g_hk[(size_t)bh*L + k0 + tid];

        __syncthreads();
        *(uint4*)&Ks[fr*HSTR + fc]     = kA;
        *(uint4*)&Ks[fr*HSTR + fc + 8] = kB;
        {
            const uint32_t* aw = (const uint32_t*)&va;
            const uint32_t* bw = (const uint32_t*)&vb;
            #pragma unroll
            for (int j=0;j<4;j++){
                uint32_t lo = __byte_perm(aw[j], bw[j], 0x5410);
                uint32_t hi = __byte_perm(aw[j], bw[j], 0x7632);
                *(uint32_t*)&Vt[(vd0+2*j  )*HSTR + 2*lane] = lo;
                *(uint32_t*)&Vt[(vd0+2*j+1)*HSTR + 2*lane] = hi;
            }
        }
        if (tid < 64) hkf[tid] = (float)hkb;
        __syncthreads();

        float S[8][4];
        #pragma unroll
        for (int nt=0;nt<8;nt++)
            #pragma unroll
            for (int c=0;c<4;c++) S[nt][c] = 0.0f;

        #pragma unroll
        for (int ks = 0; ks < 4; ks++) {
            uint32_t a0 = *(uint32_t*)&Qs[(qr+gy  )*HSTR + ks*16 + 2*gx];
            uint32_t a1 = *(uint32_t*)&Qs[(qr+gy+8)*HSTR + ks*16 + 2*gx];
            uint32_t a2 = *(uint32_t*)&Qs[(qr+gy  )*HSTR + ks*16 + 2*gx + 8];
            uint32_t a3 = *(uint32_t*)&Qs[(qr+gy+8)*HSTR + ks*16 + 2*gx + 8];
            #pragma unroll
            for (int nt = 0; nt < 8; nt++) {
                uint32_t b0 = *(uint32_t*)&Ks[(nt*8+gy)*HSTR + ks*16 + 2*gx];
                uint32_t b1 = *(uint32_t*)&Ks[(nt*8+gy)*HSTR + ks*16 + 2*gx + 8];
                mma_f16(S[nt], a0, a1, a2, a3, b0, b1);
            }
        }

        float mx0 = -INFINITY, mx1 = -INFINITY;
        #pragma unroll
        for (int nt = 0; nt < 8; nt++) {
            float fk0 = hkf[nt*8 + 2*gx];
            float fk1 = hkf[nt*8 + 2*gx + 1];
            S[nt][0] = fmaf(S[nt][0], C_SCL, -C_NEG*fabsf(fq0 - fk0));
            S[nt][1] = fmaf(S[nt][1], C_SCL, -C_NEG*fabsf(fq0 - fk1));
            S[nt][2] = fmaf(S[nt][2], C_SCL, -C_NEG*fabsf(fq1 - fk0));
            S[nt][3] = fmaf(S[nt][3], C_SCL, -C_NEG*fabsf(fq1 - fk1));
            mx0 = fmaxf(mx0, fmaxf(S[nt][0], S[nt][1]));
            mx1 = fmaxf(mx1, fmaxf(S[nt][2], S[nt][3]));
        }
        #pragma unroll
        for (int o = 1; o <= 2; o <<= 1) {
            mx0 = fmaxf(mx0, __shfl_xor_sync(0xffffffffu, mx0, o));
            mx1 = fmaxf(mx1, __shfl_xor_sync(0xffffffffu, mx1, o));
        }
        float mn0 = fmaxf(m0, mx0), mn1 = fmaxf(m1, mx1);
        float cr0 = ex2f(m0 - mn0), cr1 = ex2f(m1 - mn1);
        m0 = mn0; m1 = mn1;

        uint32_t ph0[8], ph1[8];
        float s0 = 0.0f, s1 = 0.0f;
        #pragma unroll
        for (int nt = 0; nt < 8; nt++) {
            float p0 = ex2f(S[nt][0] - mn0);
            float p1 = ex2f(S[nt][1] - mn0);
            float p2 = ex2f(S[nt][2] - mn1);
            float p3 = ex2f(S[nt][3] - mn1);
            s0 += p0 + p1; s1 += p2 + p3;
            ph0[nt] = f22h2(p0, p1);
            ph1[nt] = f22h2(p2, p3);
        }
        #pragma unroll
        for (int o = 1; o <= 2; o <<= 1) {
            s0 += __shfl_xor_sync(0xffffffffu, s0, o);
            s1 += __shfl_xor_sync(0xffffffffu, s1, o);
        }
        l0 = l0*cr0 + s0;
        l1 = l1*cr1 + s1;

        #pragma unroll
        for (int nt = 0; nt < 8; nt++) {
            O[nt][0] *= cr0; O[nt][1] *= cr0;
            O[nt][2] *= cr1; O[nt][3] *= cr1;
        }

        #pragma unroll
        for (int ks = 0; ks < 4; ks++) {
            uint32_t a0 = ph0[2*ks];
            uint32_t a1 = ph1[2*ks];
            uint32_t a2 = ph0[2*ks+1];
            uint32_t a3 = ph1[2*ks+1];
            #pragma unroll
            for (int nt = 0; nt < 8; nt++) {
                uint32_t b0 = *(uint32_t*)&Vt[(nt*8+gy)*HSTR + ks*16 + 2*gx];
                uint32_t b1 = *(uint32_t*)&Vt[(nt*8+gy)*HSTR + ks*16 + 2*gx + 8];
                mma_f16(O[nt], a0, a1, a2, a3, b0, b1);
            }
        }
    }

    const int bb = bh >> 4, hh = bh & 15;
    const float inv0 = 1.0f / l0, inv1 = 1.0f / l1;
    const int l_0 = q0 + qr + gy, l_1 = l_0 + 8;
    float* o0 = &out[((size_t)bb*L + l_0)*DIMM + hh*DH];
    float* o1 = &out[((size_t)bb*L + l_1)*DIMM + hh*DH];
    #pragma unroll
    for (int nt = 0; nt < 8; nt++) {
        *(float2*)&o0[nt*8 + 2*gx] = make_float2(O[nt][0]*inv0, O[nt][1]*inv0);
        *(float2*)&o1[nt*8 + 2*gx] = make_float2(O[nt][2]*inv1, O[nt][3]*inv1);
    }
}

// ---------------- launch ----------------
extern "C" void kernel_launch(void* const* d_in, const int* in_sizes, int n_in,
                              void* d_out, int out_size) {
    const float* X  = (const float*)d_in[0];
    const float* Wq = (const float*)d_in[1];
    const float* bq = (const float*)d_in[2];
    const float* Wv = (const float*)d_in[3];
    const float* bv = (const float*)d_in[4];
    const float* ha = (const float*)d_in[5];
    float* out = (float*)d_out;

    cudaFuncSetAttribute(proj_h_kernel, cudaFuncAttributeMaxDynamicSharedMemorySize, PROJ_SM_BYTES);
    cudaFuncSetAttribute(attn_kernel,   cudaFuncAttributeMaxDynamicSharedMemorySize, ASM_BYTES);

    __half *xh, *xl, *wqh, *wql, *wvh;
    cudaGetSymbolAddress((void**)&xh,  g_XH);
    cudaGetSymbolAddress((void**)&xl,  g_XL);
    cudaGetSymbolAddress((void**)&wqh, g_WqH);
    cudaGetSymbolAddress((void**)&wql, g_WqL);
    cudaGetSymbolAddress((void**)&wvh, g_WvH);
    cvt_kernel<<<(TOK*DIMM/4)/256, 256>>>(X,  xh,  xl,  TOK*DIMM/4, 1);
    cvt_kernel<<<(DIMM*DIMM/4)/256, 256>>>(Wq, wqh, wql, DIMM*DIMM/4, 1);
    cvt_kernel<<<(DIMM*DIMM/4)/256, 256>>>(Wv, wvh, wvh, DIMM*DIMM/4, 0);

    dim3 pg(DIMM/64, TOK/128, 2);
    proj_h_kernel<<<pg, 256, PROJ_SM_BYTES>>>(bq, bv, ha);

    hash2_kernel<<<(BH*L)/256, 256>>>(ha);

    dim3 ag(L/128, BH);
    attn_kernel<<<ag, 256, ASM_BYTES>>>(out);
}

// round 15
// speedup vs baseline: 1.2237x; 1.0846x over previous
#include <cuda_runtime.h>
#include <cuda_fp16.h>
#include <math.h>
#include <stdint.h>

#define B 2
#define L 2048
#define DIMM 1024
#define H 16
#define DH 64
#define BH (B*H)      // 32
#define TOK (B*L)     // 4096

// ---------------- scratch ----------------
__device__ __half g_qkh[BH*L*DH];
__device__ __half g_vh [BH*L*DH];
__device__ float g_dot[BH*L];
__device__ float g_norm2[BH*L];
__device__ unsigned int g_maxn2[BH];
__device__ unsigned char g_hq[BH*L];
__device__ unsigned char g_hk[BH*L];
__device__ __half g_XH [TOK*DIMM];
__device__ __half g_XL [TOK*DIMM];
__device__ __half g_WqH[DIMM*DIMM];
__device__ __half g_WqL[DIMM*DIMM];
__device__ __half g_WvH[DIMM*DIMM];

__device__ __forceinline__ uint32_t f22h2(float a, float b){
    __half2 h = __floats2half2_rn(a, b);
    return *(uint32_t*)&h;
}
__device__ __forceinline__ float ex2f(float x){
    float r; asm("ex2.approx.f32 %0, %1;" : "=f"(r) : "f"(x)); return r;
}
__device__ __forceinline__ void mma_f16(float c[4],
    uint32_t a0, uint32_t a1, uint32_t a2, uint32_t a3,
    uint32_t b0, uint32_t b1)
{
    asm("mma.sync.aligned.m16n8k16.row.col.f32.f16.f16.f32 "
        "{%0,%1,%2,%3}, {%4,%5,%6,%7}, {%8,%9}, {%0,%1,%2,%3};"
        : "+f"(c[0]), "+f"(c[1]), "+f"(c[2]), "+f"(c[3])
        : "r"(a0), "r"(a1), "r"(a2), "r"(a3), "r"(b0), "r"(b1));
}
__device__ __forceinline__ uint32_t smem_u32(const void* p){
    uint32_t a;
    asm("{ .reg .u64 t; cvta.to.shared.u64 t, %1; cvt.u32.u64 %0, t; }" : "=r"(a) : "l"(p));
    return a;
}
#define CP16(dst, src) asm volatile("cp.async.ca.shared.global [%0], [%1], 16;" :: "r"(dst), "l"(src))
#define CP_COMMIT()    asm volatile("cp.async.commit_group;" ::: "memory")
#define CP_WAIT1()     asm volatile("cp.async.wait_group 1;" ::: "memory")
#define LDSM4(r, addr) \
    asm volatile("ldmatrix.sync.aligned.m8n8.x4.shared.b16 {%0,%1,%2,%3}, [%4];" \
        : "=r"((r)[0]), "=r"((r)[1]), "=r"((r)[2]), "=r"((r)[3]) : "r"(addr))

// ============ split conversion ============
__global__ __launch_bounds__(256)
void cvt_kernel(const float* __restrict__ src, __half* __restrict__ dh,
                __half* __restrict__ dl, int n4, int makeLo)
{
    int i = blockIdx.x*blockDim.x + threadIdx.x;
    if (blockIdx.x == 0 && threadIdx.x < BH) g_maxn2[threadIdx.x] = 0u;
    if (i >= n4) return;
    float4 v = ((const float4*)src)[i];
    __half2 h0 = __floats2half2_rn(v.x, v.y);
    __half2 h1 = __floats2half2_rn(v.z, v.w);
    ((__half2*)dh)[2*i]   = h0;
    ((__half2*)dh)[2*i+1] = h1;
    if (makeLo) {
        __half2 l0 = __floats2half2_rn((v.x - __low2float(h0))*2048.0f,
                                       (v.y - __high2float(h0))*2048.0f);
        __half2 l1 = __floats2half2_rn((v.z - __low2float(h1))*2048.0f,
                                       (v.w - __high2float(h1))*2048.0f);
        ((__half2*)dl)[2*i]   = l0;
        ((__half2*)dl)[2*i+1] = l1;
    }
}

// ============ fp16 projection: cp.async + ldmatrix, 8 warps 4x2 ============
#define HP2 40
#define ST_HALVES 15360
#define ST_BYTES  30720
#define XH_O 0
#define XL_O 10240
#define WH_O 20480
#define WL_O 25600
#define PROJ_SM_BYTES (2*ST_BYTES)   // 61440

__global__ __launch_bounds__(256, 2)
void proj_h_kernel(const float* __restrict__ bq,
                   const float* __restrict__ bv,
                   const float* __restrict__ ha)
{
    extern __shared__ __half hsm[];
    const uint32_t sb = smem_u32(hsm);

    const bool SPLIT = (blockIdx.z == 0);
    __half* out = SPLIT ? g_qkh : g_vh;
    const __half* WHg = SPLIT ? g_WqH : g_WvH;
    const float* bias = SPLIT ? bq : bv;

    const int m0 = blockIdx.y * 128;
    const int n0 = blockIdx.x * 64;
    const int tid = threadIdx.x;
    const int warp = tid >> 5;
    const int lane = tid & 31;
    const int gy = lane >> 2;
    const int gx = lane & 3;
    const int wm = warp >> 1;
    const int wn = warp & 1;
    const int qr = wm * 32;
    const int nb = wn * 32;

    // cp.async fill coords
    const int xr = tid >> 1, xc = (tid & 1) * 16;
    const int wr = tid >> 2, wc = (tid & 3) * 8;

    const __half* xhp = &g_XH[(size_t)(m0+xr)*DIMM + xc];
    const __half* xlp = &g_XL[(size_t)(m0+xr)*DIMM + xc];
    const __half* whp = &WHg  [(size_t)(n0+wr)*DIMM + wc];
    const __half* wlp = &g_WqL[(size_t)(n0+wr)*DIMM + wc];

    const uint32_t dXH = sb + XH_O + ((uint32_t)xr*HP2 + xc)*2u;
    const uint32_t dXL = sb + XL_O + ((uint32_t)xr*HP2 + xc)*2u;
    const uint32_t dWH = sb + WH_O + ((uint32_t)wr*HP2 + wc)*2u;
    const uint32_t dWL = sb + WL_O + ((uint32_t)wr*HP2 + wc)*2u;

    // ldmatrix lane addresses (byte offsets within a stage)
    const int lrow = lane & 7, lmat = lane >> 3;
    const uint32_t a_off = (((uint32_t)(qr + (lmat & 1)*8 + lrow))*HP2 + (lmat >> 1)*8)*2u;
    const uint32_t aXH = sb + XH_O + a_off;
    const uint32_t aXL = sb + XL_O + a_off;
    uint32_t aWH[2], aWL[2];
    #pragma unroll
    for (int p = 0; p < 2; p++) {
        uint32_t b_off = (((uint32_t)(nb + (p*2 + (lmat >> 1))*8 + lrow))*HP2 + (lmat & 1)*8)*2u;
        aWH[p] = sb + WH_O + b_off;
        aWL[p] = sb + WL_O + b_off;
    }

    float acc1[2][4][4];
    float acc2[2][4][4];
    #pragma unroll
    for (int t=0;t<2;t++)
        #pragma unroll
        for (int nt=0;nt<4;nt++)
            #pragma unroll
            for (int c=0;c<4;c++){ acc1[t][nt][c] = 0.0f; acc2[t][nt][c] = 0.0f; }

    // prologue: fill chunk 0 into stage 0
    {
        CP16(dXH,      xhp);
        CP16(dXH + 16, xhp + 8);
        CP16(dWH,      whp);
        if (SPLIT) {
            CP16(dXL,      xlp);
            CP16(dXL + 16, xlp + 8);
            CP16(dWL,      wlp);
        }
        CP_COMMIT();
    }

    for (int c = 0; c < 32; c++) {
        if (c < 31) {
            const int kk = (c + 1) * 32;
            const uint32_t so = ((c + 1) & 1) * (uint32_t)ST_BYTES;
            CP16(dXH + so,      xhp + kk);
            CP16(dXH + so + 16, xhp + kk + 8);
            CP16(dWH + so,      whp + kk);
            if (SPLIT) {
                CP16(dXL + so,      xlp + kk);
                CP16(dXL + so + 16, xlp + kk + 8);
                CP16(dWL + so,      wlp + kk);
            }
        }
        CP_COMMIT();
        CP_WAIT1();
        __syncthreads();

        const uint32_t so2 = (c & 1) * (uint32_t)ST_BYTES;

        #pragma unroll
        for (int ks = 0; ks < 2; ks++) {
            const uint32_t ko = (uint32_t)ks * 32u;   // ks*16 halves
            uint32_t ah[2][4], al[2][4];
            #pragma unroll
            for (int t = 0; t < 2; t++) {
                LDSM4(ah[t], aXH + so2 + (uint32_t)t*1280u + ko);
                if (SPLIT) LDSM4(al[t], aXL + so2 + (uint32_t)t*1280u + ko);
            }
            #pragma unroll
            for (int p = 0; p < 2; p++) {
                uint32_t bh4[4], bl4[4];
                LDSM4(bh4, aWH[p] + so2 + ko);
                if (SPLIT) LDSM4(bl4, aWL[p] + so2 + ko);
                #pragma unroll
                for (int q = 0; q < 2; q++) {
                    const int nt = p*2 + q;
                    uint32_t bh0 = bh4[q*2], bh1 = bh4[q*2+1];
                    #pragma unroll
                    for (int t = 0; t < 2; t++) {
                        mma_f16(acc1[t][nt], ah[t][0], ah[t][1], ah[t][2], ah[t][3], bh0, bh1);
                        if (SPLIT) {
                            mma_f16(acc2[t][nt], ah[t][0], ah[t][1], ah[t][2], ah[t][3], bl4[q*2], bl4[q*2+1]);
                            mma_f16(acc2[t][nt], al[t][0], al[t][1], al[t][2], al[t][3], bh0, bh1);
                        }
                    }
                }
            }
        }
        __syncthreads();
    }

    // ---- epilogue: bias, fp16 store, hash partials ----
    const int hh = blockIdx.x;
    const float inv2048 = 1.0f/2048.0f;
    float* pd = (float*)hsm;
    float* pn = pd + 256;

    #pragma unroll
    for (int t = 0; t < 2; t++) {
        const int r_0 = qr + t*16 + gy;
        const int r_1 = r_0 + 8;
        const int m_0 = m0 + r_0, m_1 = m0 + r_1;
        const int b0_ = m_0 >> 11, l0_ = m_0 & (L-1);
        const int b1_ = m_1 >> 11, l1_ = m_1 & (L-1);
        __half* o0 = &out[(((size_t)(b0_*H + hh)*L + l0_)*DH)];
        __half* o1 = &out[(((size_t)(b1_*H + hh)*L + l1_)*DH)];

        float dot0 = 0.f, n20 = 0.f, dot1 = 0.f, n21 = 0.f;
        #pragma unroll
        for (int nt = 0; nt < 4; nt++) {
            int col = nb + nt*8 + 2*gx;
            float bs0 = bias[hh*64 + col];
            float bs1 = bias[hh*64 + col + 1];
            float v00, v01, v10, v11;
            if (SPLIT) {
                v00 = fmaf(acc2[t][nt][0], inv2048, acc1[t][nt][0]) + bs0;
                v01 = fmaf(acc2[t][nt][1], inv2048, acc1[t][nt][1]) + bs1;
                v10 = fmaf(acc2[t][nt][2], inv2048, acc1[t][nt][2]) + bs0;
                v11 = fmaf(acc2[t][nt][3], inv2048, acc1[t][nt][3]) + bs1;
            } else {
                v00 = acc1[t][nt][0] + bs0; v01 = acc1[t][nt][1] + bs1;
                v10 = acc1[t][nt][2] + bs0; v11 = acc1[t][nt][3] + bs1;
            }
            *(uint32_t*)&o0[col] = f22h2(v00, v01);
            *(uint32_t*)&o1[col] = f22h2(v10, v11);
            if (SPLIT) {
                float a0 = ha[col], a1 = ha[col + 1];
                dot0 = fmaf(v00, a0, fmaf(v01, a1, dot0));
                dot1 = fmaf(v10, a0, fmaf(v11, a1, dot1));
                n20  = fmaf(v00, v00, fmaf(v01, v01, n20));
                n21  = fmaf(v10, v10, fmaf(v11, v11, n21));
            }
        }
        if (SPLIT) {
            #pragma unroll
            for (int o = 1; o <= 2; o <<= 1) {
                dot0 += __shfl_xor_sync(0xffffffffu, dot0, o);
                dot1 += __shfl_xor_sync(0xffffffffu, dot1, o);
                n20  += __shfl_xor_sync(0xffffffffu, n20, o);
                n21  += __shfl_xor_sync(0xffffffffu, n21, o);
            }
            if (gx == 0) {
                pd[r_0*2 + wn] = dot0;  pn[r_0*2 + wn] = n20;
                pd[r_1*2 + wn] = dot1;  pn[r_1*2 + wn] = n21;
            }
        }
    }
    if (SPLIT) {
        __syncthreads();
        if (tid < 128) {
            int r = tid;
            float dot = pd[r*2] + pd[r*2+1];
            float n2  = pn[r*2] + pn[r*2+1];
            int m = m0 + r;
            int bb = m >> 11, ll = m & (L-1);
            size_t gw = (size_t)(bb*H + hh)*L + ll;
            g_dot[gw] = dot;
            g_norm2[gw] = n2;
            atomicMax(&g_maxn2[bb*H + hh], __float_as_uint(n2));
        }
    }
}

// ---------------- hash ----------------
__global__ void hash2_kernel(const float* __restrict__ ha) {
    int t = blockIdx.x * blockDim.x + threadIdx.x;
    if (t >= BH*L) return;
    float dot = g_dot[t], n2 = g_norm2[t];
    float maxn = sqrtf(__uint_as_float(g_maxn2[t >> 11]));
    float s = 0.75f / fmaxf(maxn, 1e-12f);
    float nk2 = s*s*n2;
    float hkval = s*dot + (0.5f - nk2)*ha[DH] + (0.5f - nk2*nk2)*ha[DH+1];
    g_hq[t] = (dot   >= 0.0f) ? 1 : 0;
    g_hk[t] = (hkval >= 0.0f) ? 1 : 0;
}

// ============ fp16 flash attention (unchanged from R10) ============
#define HSTR 72
#define QS_OFF 0
#define KS_OFF (128*HSTR)
#define VT_OFF (KS_OFF + 64*HSTR)
#define HK_OFF (VT_OFF + 64*HSTR)
#define ASM_HALVES (HK_OFF + 128)
#define ASM_BYTES (ASM_HALVES*2)

#define C_SCL 0.1803368801111713f
#define C_NEG 14426.950408889634f

__global__ __launch_bounds__(256, 2)
void attn_kernel(float* __restrict__ out) {
    extern __shared__ __half smh[];
    __half* Qs = smh + QS_OFF;
    __half* Ks = smh + KS_OFF;
    __half* Vt = smh + VT_OFF;
    float* hkf = (float*)(smh + HK_OFF);

    const int bh = blockIdx.y;
    const int q0 = blockIdx.x * 128;
    const int tid = threadIdx.x;
    const int warp = tid >> 5;
    const int lane = tid & 31;
    const int gy = lane >> 2;
    const int gx = lane & 3;
    const int qr = warp * 16;

    {
        int r = tid >> 1, c0 = (tid & 1) * 32;
        const __half* qp = &g_qkh[((size_t)bh*L + q0 + r)*DH + c0];
        #pragma unroll
        for (int c8 = 0; c8 < 4; c8++)
            *(uint4*)&Qs[r*HSTR + c0 + c8*8] = *(const uint4*)&qp[c8*8];
    }

    const float fq0 = (float)g_hq[(size_t)bh*L + q0 + qr + gy];
    const float fq1 = (float)g_hq[(size_t)bh*L + q0 + qr + gy + 8];

    float O[8][4];
    #pragma unroll
    for (int nt=0;nt<8;nt++)
        #pragma unroll
        for (int c=0;c<4;c++) O[nt][c] = 0.0f;
    float m0 = -INFINITY, m1 = -INFINITY, l0 = 0.0f, l1 = 0.0f;

    const int fr = tid >> 2;
    const int fc = (tid & 3) * 16;
    const int vd0 = warp * 8;

    for (int k0 = 0; k0 < L; k0 += 64) {
        uint4 kA, kB;
        {
            const __half* kp = &g_qkh[((size_t)bh*L + k0 + fr)*DH + fc];
            kA = ((const uint4*)kp)[0];
            kB = ((const uint4*)kp)[1];
        }
        uint4 va, vb;
        {
            const __half* vp = &g_vh[((size_t)bh*L + k0 + 2*lane)*DH + vd0];
            va = *(const uint4*)vp;
            vb = *(const uint4*)(vp + DH);
        }
        unsigned char hkb = 0;
        if (tid < 64) hkb = g_hk[(size_t)bh*L + k0 + tid];

        __syncthreads();
        *(uint4*)&Ks[fr*HSTR + fc]     = kA;
        *(uint4*)&Ks[fr*HSTR + fc + 8] = kB;
        {
            const uint32_t* aw = (const uint32_t*)&va;
            const uint32_t* bw = (const uint32_t*)&vb;
            #pragma unroll
            for (int j=0;j<4;j++){
                uint32_t lo = __byte_perm(aw[j], bw[j], 0x5410);
                uint32_t hi = __byte_perm(aw[j], bw[j], 0x7632);
                *(uint32_t*)&Vt[(vd0+2*j  )*HSTR + 2*lane] = lo;
                *(uint32_t*)&Vt[(vd0+2*j+1)*HSTR + 2*lane] = hi;
            }
        }
        if (tid < 64) hkf[tid] = (float)hkb;
        __syncthreads();

        float S[8][4];
        #pragma unroll
        for (int nt=0;nt<8;nt++)
            #pragma unroll
            for (int c=0;c<4;c++) S[nt][c] = 0.0f;

        #pragma unroll
        for (int ks = 0; ks < 4; ks++) {
            uint32_t a0 = *(uint32_t*)&Qs[(qr+gy  )*HSTR + ks*16 + 2*gx];
            uint32_t a1 = *(uint32_t*)&Qs[(qr+gy+8)*HSTR + ks*16 + 2*gx];
            uint32_t a2 = *(uint32_t*)&Qs[(qr+gy  )*HSTR + ks*16 + 2*gx + 8];
            uint32_t a3 = *(uint32_t*)&Qs[(qr+gy+8)*HSTR + ks*16 + 2*gx + 8];
            #pragma unroll
            for (int nt = 0; nt < 8; nt++) {
                uint32_t b0 = *(uint32_t*)&Ks[(nt*8+gy)*HSTR + ks*16 + 2*gx];
                uint32_t b1 = *(uint32_t*)&Ks[(nt*8+gy)*HSTR + ks*16 + 2*gx + 8];
                mma_f16(S[nt], a0, a1, a2, a3, b0, b1);
            }
        }

        float mx0 = -INFINITY, mx1 = -INFINITY;
        #pragma unroll
        for (int nt = 0; nt < 8; nt++) {
            float fk0 = hkf[nt*8 + 2*gx];
            float fk1 = hkf[nt*8 + 2*gx + 1];
            S[nt][0] = fmaf(S[nt][0], C_SCL, -C_NEG*fabsf(fq0 - fk0));
            S[nt][1] = fmaf(S[nt][1], C_SCL, -C_NEG*fabsf(fq0 - fk1));
            S[nt][2] = fmaf(S[nt][2], C_SCL, -C_NEG*fabsf(fq1 - fk0));
            S[nt][3] = fmaf(S[nt][3], C_SCL, -C_NEG*fabsf(fq1 - fk1));
            mx0 = fmaxf(mx0, fmaxf(S[nt][0], S[nt][1]));
            mx1 = fmaxf(mx1, fmaxf(S[nt][2], S[nt][3]));
        }
        #pragma unroll
        for (int o = 1; o <= 2; o <<= 1) {
            mx0 = fmaxf(mx0, __shfl_xor_sync(0xffffffffu, mx0, o));
            mx1 = fmaxf(mx1, __shfl_xor_sync(0xffffffffu, mx1, o));
        }
        float mn0 = fmaxf(m0, mx0), mn1 = fmaxf(m1, mx1);
        float cr0 = ex2f(m0 - mn0), cr1 = ex2f(m1 - mn1);
        m0 = mn0; m1 = mn1;

        uint32_t ph0[8], ph1[8];
        float s0 = 0.0f, s1 = 0.0f;
        #pragma unroll
        for (int nt = 0; nt < 8; nt++) {
            float p0 = ex2f(S[nt][0] - mn0);
            float p1 = ex2f(S[nt][1] - mn0);
            float p2 = ex2f(S[nt][2] - mn1);
            float p3 = ex2f(S[nt][3] - mn1);
            s0 += p0 + p1; s1 += p2 + p3;
            ph0[nt] = f22h2(p0, p1);
            ph1[nt] = f22h2(p2, p3);
        }
        #pragma unroll
        for (int o = 1; o <= 2; o <<= 1) {
            s0 += __shfl_xor_sync(0xffffffffu, s0, o);
            s1 += __shfl_xor_sync(0xffffffffu, s1, o);
        }
        l0 = l0*cr0 + s0;
        l1 = l1*cr1 + s1;

        #pragma unroll
        for (int nt = 0; nt < 8; nt++) {
            O[nt][0] *= cr0; O[nt][1] *= cr0;
            O[nt][2] *= cr1; O[nt][3] *= cr1;
        }

        #pragma unroll
        for (int ks = 0; ks < 4; ks++) {
            uint32_t a0 = ph0[2*ks];
            uint32_t a1 = ph1[2*ks];
            uint32_t a2 = ph0[2*ks+1];
            uint32_t a3 = ph1[2*ks+1];
            #pragma unroll
            for (int nt = 0; nt < 8; nt++) {
                uint32_t b0 = *(uint32_t*)&Vt[(nt*8+gy)*HSTR + ks*16 + 2*gx];
                uint32_t b1 = *(uint32_t*)&Vt[(nt*8+gy)*HSTR + ks*16 + 2*gx + 8];
                mma_f16(O[nt], a0, a1, a2, a3, b0, b1);
            }
        }
    }

    const int bb = bh >> 4, hh = bh & 15;
    const float inv0 = 1.0f / l0, inv1 = 1.0f / l1;
    const int l_0 = q0 + qr + gy, l_1 = l_0 + 8;
    float* o0 = &out[((size_t)bb*L + l_0)*DIMM + hh*DH];
    float* o1 = &out[((size_t)bb*L + l_1)*DIMM + hh*DH];
    #pragma unroll
    for (int nt = 0; nt < 8; nt++) {
        *(float2*)&o0[nt*8 + 2*gx] = make_float2(O[nt][0]*inv0, O[nt][1]*inv0);
        *(float2*)&o1[nt*8 + 2*gx] = make_float2(O[nt][2]*inv1, O[nt][3]*inv1);
    }
}

// ---------------- launch ----------------
extern "C" void kernel_launch(void* const* d_in, const int* in_sizes, int n_in,
                              void* d_out, int out_size) {
    const float* X  = (const float*)d_in[0];
    const float* Wq = (const float*)d_in[1];
    const float* bq = (const float*)d_in[2];
    const float* Wv = (const float*)d_in[3];
    const float* bv = (const float*)d_in[4];
    const float* ha = (const float*)d_in[5];
    float* out = (float*)d_out;

    cudaFuncSetAttribute(proj_h_kernel, cudaFuncAttributeMaxDynamicSharedMemorySize, PROJ_SM_BYTES);
    cudaFuncSetAttribute(attn_kernel,   cudaFuncAttributeMaxDynamicSharedMemorySize, ASM_BYTES);

    __half *xh, *xl, *wqh, *wql, *wvh;
    cudaGetSymbolAddress((void**)&xh,  g_XH);
    cudaGetSymbolAddress((void**)&xl,  g_XL);
    cudaGetSymbolAddress((void**)&wqh, g_WqH);
    cudaGetSymbolAddress((void**)&wql, g_WqL);
    cudaGetSymbolAddress((void**)&wvh, g_WvH);
    cvt_kernel<<<(TOK*DIMM/4)/256, 256>>>(X,  xh,  xl,  TOK*DIMM/4, 1);
    cvt_kernel<<<(DIMM*DIMM/4)/256, 256>>>(Wq, wqh, wql, DIMM*DIMM/4, 1);
    cvt_kernel<<<(DIMM*DIMM/4)/256, 256>>>(Wv, wvh, wvh, DIMM*DIMM/4, 0);

    dim3 pg(DIMM/64, TOK/128, 2);
    proj_h_kernel<<<pg, 256, PROJ_SM_BYTES>>>(bq, bv, ha);

    hash2_kernel<<<(BH*L)/256, 256>>>(ha);

    dim3 ag(L/128, BH);
    attn_kernel<<<ag, 256, ASM_BYTES>>>(out);
}

// round 16
// speedup vs baseline: 1.3848x; 1.1317x over previous
#include <cuda_runtime.h>
#include <cuda_fp16.h>
#include <math.h>
#include <stdint.h>

#define B 2
#define L 2048
#define DIMM 1024
#define H 16
#define DH 64
#define BH (B*H)      // 32
#define TOK (B*L)     // 4096

// ---------------- scratch ----------------
__device__ __half g_qkh[BH*L*DH];
__device__ __half g_vh [BH*L*DH];
__device__ float g_dot[BH*L];
__device__ float g_norm2[BH*L];
__device__ unsigned int g_maxn2[BH];
__device__ unsigned char g_hq[BH*L];
__device__ unsigned char g_hk[BH*L];
__device__ __half g_XH [TOK*DIMM];
__device__ __half g_XL [TOK*DIMM];
__device__ __half g_WqH[DIMM*DIMM];
__device__ __half g_WqL[DIMM*DIMM];
__device__ __half g_WvH[DIMM*DIMM];

__device__ __forceinline__ uint32_t f22h2(float a, float b){
    __half2 h = __floats2half2_rn(a, b);
    return *(uint32_t*)&h;
}
__device__ __forceinline__ float ex2f(float x){
    float r; asm("ex2.approx.f32 %0, %1;" : "=f"(r) : "f"(x)); return r;
}
__device__ __forceinline__ void mma_f16(float c[4],
    uint32_t a0, uint32_t a1, uint32_t a2, uint32_t a3,
    uint32_t b0, uint32_t b1)
{
    asm("mma.sync.aligned.m16n8k16.row.col.f32.f16.f16.f32 "
        "{%0,%1,%2,%3}, {%4,%5,%6,%7}, {%8,%9}, {%0,%1,%2,%3};"
        : "+f"(c[0]), "+f"(c[1]), "+f"(c[2]), "+f"(c[3])
        : "r"(a0), "r"(a1), "r"(a2), "r"(a3), "r"(b0), "r"(b1));
}
__device__ __forceinline__ uint32_t smem_u32(const void* p){
    uint32_t a;
    asm("{ .reg .u64 t; cvta.to.shared.u64 t, %1; cvt.u32.u64 %0, t; }" : "=r"(a) : "l"(p));
    return a;
}
#define CP16(dst, src) asm volatile("cp.async.ca.shared.global [%0], [%1], 16;" :: "r"(dst), "l"(src))
#define CP4(dst, src)  asm volatile("cp.async.ca.shared.global [%0], [%1], 4;"  :: "r"(dst), "l"(src))
#define CP_COMMIT()    asm volatile("cp.async.commit_group;" ::: "memory")
#define CP_WAIT1()     asm volatile("cp.async.wait_group 1;" ::: "memory")
#define LDSM4(r, addr) \
    asm volatile("ldmatrix.sync.aligned.m8n8.x4.shared.b16 {%0,%1,%2,%3}, [%4];" \
        : "=r"((r)[0]), "=r"((r)[1]), "=r"((r)[2]), "=r"((r)[3]) : "r"(addr))
#define LDSM4T(r, addr) \
    asm volatile("ldmatrix.sync.aligned.m8n8.x4.trans.shared.b16 {%0,%1,%2,%3}, [%4];" \
        : "=r"((r)[0]), "=r"((r)[1]), "=r"((r)[2]), "=r"((r)[3]) : "r"(addr))

// ============ split conversion ============
__global__ __launch_bounds__(256)
void cvt_kernel(const float* __restrict__ src, __half* __restrict__ dh,
                __half* __restrict__ dl, int n4, int makeLo)
{
    int i = blockIdx.x*blockDim.x + threadIdx.x;
    if (blockIdx.x == 0 && threadIdx.x < BH) g_maxn2[threadIdx.x] = 0u;
    if (i >= n4) return;
    float4 v = ((const float4*)src)[i];
    __half2 h0 = __floats2half2_rn(v.x, v.y);
    __half2 h1 = __floats2half2_rn(v.z, v.w);
    ((__half2*)dh)[2*i]   = h0;
    ((__half2*)dh)[2*i+1] = h1;
    if (makeLo) {
        __half2 l0 = __floats2half2_rn((v.x - __low2float(h0))*2048.0f,
                                       (v.y - __high2float(h0))*2048.0f);
        __half2 l1 = __floats2half2_rn((v.z - __low2float(h1))*2048.0f,
                                       (v.w - __high2float(h1))*2048.0f);
        ((__half2*)dl)[2*i]   = l0;
        ((__half2*)dl)[2*i+1] = l1;
    }
}

// ============ fp16 projection (unchanged from R15) ============
#define HP2 40
#define ST_HALVES 15360
#define ST_BYTES  30720
#define XH_O 0
#define XL_O 10240
#define WH_O 20480
#define WL_O 25600
#define PROJ_SM_BYTES (2*ST_BYTES)

__global__ __launch_bounds__(256, 2)
void proj_h_kernel(const float* __restrict__ bq,
                   const float* __restrict__ bv,
                   const float* __restrict__ ha)
{
    extern __shared__ __half hsm[];
    const uint32_t sb = smem_u32(hsm);

    const bool SPLIT = (blockIdx.z == 0);
    __half* out = SPLIT ? g_qkh : g_vh;
    const __half* WHg = SPLIT ? g_WqH : g_WvH;
    const float* bias = SPLIT ? bq : bv;

    const int m0 = blockIdx.y * 128;
    const int n0 = blockIdx.x * 64;
    const int tid = threadIdx.x;
    const int warp = tid >> 5;
    const int lane = tid & 31;
    const int gy = lane >> 2;
    const int gx = lane & 3;
    const int wm = warp >> 1;
    const int wn = warp & 1;
    const int qr = wm * 32;
    const int nb = wn * 32;

    const int xr = tid >> 1, xc = (tid & 1) * 16;
    const int wr = tid >> 2, wc = (tid & 3) * 8;

    const __half* xhp = &g_XH[(size_t)(m0+xr)*DIMM + xc];
    const __half* xlp = &g_XL[(size_t)(m0+xr)*DIMM + xc];
    const __half* whp = &WHg  [(size_t)(n0+wr)*DIMM + wc];
    const __half* wlp = &g_WqL[(size_t)(n0+wr)*DIMM + wc];

    const uint32_t dXH = sb + XH_O + ((uint32_t)xr*HP2 + xc)*2u;
    const uint32_t dXL = sb + XL_O + ((uint32_t)xr*HP2 + xc)*2u;
    const uint32_t dWH = sb + WH_O + ((uint32_t)wr*HP2 + wc)*2u;
    const uint32_t dWL = sb + WL_O + ((uint32_t)wr*HP2 + wc)*2u;

    const int lrow = lane & 7, lmat = lane >> 3;
    const uint32_t a_off = (((uint32_t)(qr + (lmat & 1)*8 + lrow))*HP2 + (lmat >> 1)*8)*2u;
    const uint32_t aXH = sb + XH_O + a_off;
    const uint32_t aXL = sb + XL_O + a_off;
    uint32_t aWH[2], aWL[2];
    #pragma unroll
    for (int p = 0; p < 2; p++) {
        uint32_t b_off = (((uint32_t)(nb + (p*2 + (lmat >> 1))*8 + lrow))*HP2 + (lmat & 1)*8)*2u;
        aWH[p] = sb + WH_O + b_off;
        aWL[p] = sb + WL_O + b_off;
    }

    float acc1[2][4][4];
    float acc2[2][4][4];
    #pragma unroll
    for (int t=0;t<2;t++)
        #pragma unroll
        for (int nt=0;nt<4;nt++)
            #pragma unroll
            for (int c=0;c<4;c++){ acc1[t][nt][c] = 0.0f; acc2[t][nt][c] = 0.0f; }

    {
        CP16(dXH,      xhp);
        CP16(dXH + 16, xhp + 8);
        CP16(dWH,      whp);
        if (SPLIT) {
            CP16(dXL,      xlp);
            CP16(dXL + 16, xlp + 8);
            CP16(dWL,      wlp);
        }
        CP_COMMIT();
    }

    for (int c = 0; c < 32; c++) {
        if (c < 31) {
            const int kk = (c + 1) * 32;
            const uint32_t so = ((c + 1) & 1) * (uint32_t)ST_BYTES;
            CP16(dXH + so,      xhp + kk);
            CP16(dXH + so + 16, xhp + kk + 8);
            CP16(dWH + so,      whp + kk);
            if (SPLIT) {
                CP16(dXL + so,      xlp + kk);
                CP16(dXL + so + 16, xlp + kk + 8);
                CP16(dWL + so,      wlp + kk);
            }
        }
        CP_COMMIT();
        CP_WAIT1();
        __syncthreads();

        const uint32_t so2 = (c & 1) * (uint32_t)ST_BYTES;

        #pragma unroll
        for (int ks = 0; ks < 2; ks++) {
            const uint32_t ko = (uint32_t)ks * 32u;
            uint32_t ah[2][4], al[2][4];
            #pragma unroll
            for (int t = 0; t < 2; t++) {
                LDSM4(ah[t], aXH + so2 + (uint32_t)t*1280u + ko);
                if (SPLIT) LDSM4(al[t], aXL + so2 + (uint32_t)t*1280u + ko);
            }
            #pragma unroll
            for (int p = 0; p < 2; p++) {
                uint32_t bh4[4], bl4[4];
                LDSM4(bh4, aWH[p] + so2 + ko);
                if (SPLIT) LDSM4(bl4, aWL[p] + so2 + ko);
                #pragma unroll
                for (int q = 0; q < 2; q++) {
                    const int nt = p*2 + q;
                    uint32_t bh0 = bh4[q*2], bh1 = bh4[q*2+1];
                    #pragma unroll
                    for (int t = 0; t < 2; t++) {
                        mma_f16(acc1[t][nt], ah[t][0], ah[t][1], ah[t][2], ah[t][3], bh0, bh1);
                        if (SPLIT) {
                            mma_f16(acc2[t][nt], ah[t][0], ah[t][1], ah[t][2], ah[t][3], bl4[q*2], bl4[q*2+1]);
                            mma_f16(acc2[t][nt], al[t][0], al[t][1], al[t][2], al[t][3], bh0, bh1);
                        }
                    }
                }
            }
        }
        __syncthreads();
    }

    const int hh = blockIdx.x;
    const float inv2048 = 1.0f/2048.0f;
    float* pd = (float*)hsm;
    float* pn = pd + 256;

    #pragma unroll
    for (int t = 0; t < 2; t++) {
        const int r_0 = qr + t*16 + gy;
        const int r_1 = r_0 + 8;
        const int m_0 = m0 + r_0, m_1 = m0 + r_1;
        const int b0_ = m_0 >> 11, l0_ = m_0 & (L-1);
        const int b1_ = m_1 >> 11, l1_ = m_1 & (L-1);
        __half* o0 = &out[(((size_t)(b0_*H + hh)*L + l0_)*DH)];
        __half* o1 = &out[(((size_t)(b1_*H + hh)*L + l1_)*DH)];

        float dot0 = 0.f, n20 = 0.f, dot1 = 0.f, n21 = 0.f;
        #pragma unroll
        for (int nt = 0; nt < 4; nt++) {
            int col = nb + nt*8 + 2*gx;
            float bs0 = bias[hh*64 + col];
            float bs1 = bias[hh*64 + col + 1];
            float v00, v01, v10, v11;
            if (SPLIT) {
                v00 = fmaf(acc2[t][nt][0], inv2048, acc1[t][nt][0]) + bs0;
                v01 = fmaf(acc2[t][nt][1], inv2048, acc1[t][nt][1]) + bs1;
                v10 = fmaf(acc2[t][nt][2], inv2048, acc1[t][nt][2]) + bs0;
                v11 = fmaf(acc2[t][nt][3], inv2048, acc1[t][nt][3]) + bs1;
            } else {
                v00 = acc1[t][nt][0] + bs0; v01 = acc1[t][nt][1] + bs1;
                v10 = acc1[t][nt][2] + bs0; v11 = acc1[t][nt][3] + bs1;
            }
            *(uint32_t*)&o0[col] = f22h2(v00, v01);
            *(uint32_t*)&o1[col] = f22h2(v10, v11);
            if (SPLIT) {
                float a0 = ha[col], a1 = ha[col + 1];
                dot0 = fmaf(v00, a0, fmaf(v01, a1, dot0));
                dot1 = fmaf(v10, a0, fmaf(v11, a1, dot1));
                n20  = fmaf(v00, v00, fmaf(v01, v01, n20));
                n21  = fmaf(v10, v10, fmaf(v11, v11, n21));
            }
        }
        if (SPLIT) {
            #pragma unroll
            for (int o = 1; o <= 2; o <<= 1) {
                dot0 += __shfl_xor_sync(0xffffffffu, dot0, o);
                dot1 += __shfl_xor_sync(0xffffffffu, dot1, o);
                n20  += __shfl_xor_sync(0xffffffffu, n20, o);
                n21  += __shfl_xor_sync(0xffffffffu, n21, o);
            }
            if (gx == 0) {
                pd[r_0*2 + wn] = dot0;  pn[r_0*2 + wn] = n20;
                pd[r_1*2 + wn] = dot1;  pn[r_1*2 + wn] = n21;
            }
        }
    }
    if (SPLIT) {
        __syncthreads();
        if (tid < 128) {
            int r = tid;
            float dot = pd[r*2] + pd[r*2+1];
            float n2  = pn[r*2] + pn[r*2+1];
            int m = m0 + r;
            int bb = m >> 11, ll = m & (L-1);
            size_t gw = (size_t)(bb*H + hh)*L + ll;
            g_dot[gw] = dot;
            g_norm2[gw] = n2;
            atomicMax(&g_maxn2[bb*H + hh], __float_as_uint(n2));
        }
    }
}

// ---------------- hash ----------------
__global__ void hash2_kernel(const float* __restrict__ ha) {
    int t = blockIdx.x * blockDim.x + threadIdx.x;
    if (t >= BH*L) return;
    float dot = g_dot[t], n2 = g_norm2[t];
    float maxn = sqrtf(__uint_as_float(g_maxn2[t >> 11]));
    float s = 0.75f / fmaxf(maxn, 1e-12f);
    float nk2 = s*s*n2;
    float hkval = s*dot + (0.5f - nk2)*ha[DH] + (0.5f - nk2*nk2)*ha[DH+1];
    g_hq[t] = (dot   >= 0.0f) ? 1 : 0;
    g_hk[t] = (hkval >= 0.0f) ? 1 : 0;
}

// ============ fp16 flash attention: cp.async + ldmatrix ============
// smem (bytes): Q[128][72] @0 (18432) | K 2x[64][72] @18432 | V 2x[64][72] @36864 | hk 2x64 @55296
#define AQ_B 0
#define AK_B 18432
#define AV_B 36864
#define AHK_B 55296
#define AST_B 9216            // one K or V stage
#define ASM_BYTES 55552

#define C_SCL 0.1803368801111713f
#define C_NEG 14426.950408889634f

__global__ __launch_bounds__(256, 2)
void attn_kernel(float* __restrict__ out) {
    extern __shared__ __half smh[];
    const uint32_t sb = smem_u32(smh);

    const int bh = blockIdx.y;
    const int q0 = blockIdx.x * 128;
    const int tid = threadIdx.x;
    const int warp = tid >> 5;
    const int lane = tid & 31;
    const int gy = lane >> 2;
    const int gx = lane & 3;
    const int qr = warp * 16;

    // ---- Q fill (once): plain fp16 copy into [128][72] ----
    {
        int r = tid >> 1, c0 = (tid & 1) * 32;
        const __half* qp = &g_qkh[((size_t)bh*L + q0 + r)*DH + c0];
        #pragma unroll
        for (int c8 = 0; c8 < 4; c8++)
            *(uint4*)&smh[r*72 + c0 + c8*8] = *(const uint4*)&qp[c8*8];
    }

    const int hq0 = g_hq[(size_t)bh*L + q0 + qr + gy];
    const int hq1 = g_hq[(size_t)bh*L + q0 + qr + gy + 8];

    // cp.async fill coords: 512 16B-chunks per tile, 2 per thread
    const int fr0 = tid >> 3,        fo0 = (tid & 7) * 8;          // halves
    const int fr1 = (tid + 256) >> 3, fo1 = ((tid + 256) & 7) * 8;
    const __half* kbase = &g_qkh[(size_t)bh*L*DH];
    const __half* vbase = &g_vh [(size_t)bh*L*DH];
    const uint32_t dK0 = sb + AK_B + ((uint32_t)fr0*72 + fo0)*2u;
    const uint32_t dK1 = sb + AK_B + ((uint32_t)fr1*72 + fo1)*2u;
    const uint32_t dV0 = sb + AV_B + ((uint32_t)fr0*72 + fo0)*2u;
    const uint32_t dV1 = sb + AV_B + ((uint32_t)fr1*72 + fo1)*2u;

    // ldmatrix addresses
    const int lrow = lane & 7, lmat = lane >> 3;
    const uint32_t aQ = sb + AQ_B + (((uint32_t)(qr + (lmat & 1)*8 + lrow))*72u + (lmat >> 1)*8u)*2u;
    uint32_t aK[4], aV[4];
    #pragma unroll
    for (int p = 0; p < 4; p++) {
        aK[p] = sb + AK_B + (((uint32_t)((p*2 + (lmat >> 1))*8 + lrow))*72u + (lmat & 1)*8u)*2u;
        aV[p] = sb + AV_B + (((uint32_t)((lmat & 1)*8 + lrow))*72u + (uint32_t)(p*2 + (lmat >> 1))*8u)*2u;
    }

    float O[8][4];
    #pragma unroll
    for (int nt=0;nt<8;nt++)
        #pragma unroll
        for (int c=0;c<4;c++) O[nt][c] = 0.0f;
    float m0 = -INFINITY, m1 = -INFINITY, l0 = 0.0f, l1 = 0.0f;

    // prologue: fill tile 0 into stage 0
    {
        CP16(dK0, kbase + (size_t)fr0*DH + fo0);
        CP16(dK1, kbase + (size_t)fr1*DH + fo1);
        CP16(dV0, vbase + (size_t)fr0*DH + fo0);
        CP16(dV1, vbase + (size_t)fr1*DH + fo1);
        if (tid < 16) CP4(sb + AHK_B + tid*4, &g_hk[(size_t)bh*L + tid*4]);
        CP_COMMIT();
    }

    for (int it = 0; it < 32; it++) {
        const int k0 = it * 64;
        if (it < 31) {
            const size_t kn = (size_t)(k0 + 64) * DH;
            const uint32_t so = ((it + 1) & 1) * (uint32_t)AST_B;
            CP16(dK0 + so, kbase + kn + (size_t)fr0*DH + fo0);
            CP16(dK1 + so, kbase + kn + (size_t)fr1*DH + fo1);
            CP16(dV0 + so, vbase + kn + (size_t)fr0*DH + fo0);
            CP16(dV1 + so, vbase + kn + (size_t)fr1*DH + fo1);
            if (tid < 16) CP4(sb + AHK_B + ((it+1)&1)*64 + tid*4,
                              &g_hk[(size_t)bh*L + k0 + 64 + tid*4]);
        }
        CP_COMMIT();
        CP_WAIT1();
        __syncthreads();

        const uint32_t so2 = (it & 1) * (uint32_t)AST_B;
        const unsigned char* hks = (const unsigned char*)smh + AHK_B + (it & 1)*64;

        // ---- S = Q @ K^T ----
        float S[8][4];
        #pragma unroll
        for (int nt=0;nt<8;nt++)
            #pragma unroll
            for (int c=0;c<4;c++) S[nt][c] = 0.0f;

        #pragma unroll
        for (int ks = 0; ks < 4; ks++) {
            const uint32_t ko = (uint32_t)ks * 32u;
            uint32_t a4[4];
            LDSM4(a4, aQ + ko);
            #pragma unroll
            for (int p = 0; p < 4; p++) {
                uint32_t b4[4];
                LDSM4(b4, aK[p] + so2 + ko);
                mma_f16(S[p*2  ], a4[0], a4[1], a4[2], a4[3], b4[0], b4[1]);
                mma_f16(S[p*2+1], a4[0], a4[1], a4[2], a4[3], b4[2], b4[3]);
            }
        }

        // ---- mask + scale (base-2 domain); row max ----
        float mx0 = -INFINITY, mx1 = -INFINITY;
        #pragma unroll
        for (int nt = 0; nt < 8; nt++) {
            int k0b = hks[nt*8 + 2*gx];
            int k1b = hks[nt*8 + 2*gx + 1];
            S[nt][0] = fmaf(S[nt][0], C_SCL, (hq0 == k0b) ? 0.0f : -C_NEG);
            S[nt][1] = fmaf(S[nt][1], C_SCL, (hq0 == k1b) ? 0.0f : -C_NEG);
            S[nt][2] = fmaf(S[nt][2], C_SCL, (hq1 == k0b) ? 0.0f : -C_NEG);
            S[nt][3] = fmaf(S[nt][3], C_SCL, (hq1 == k1b) ? 0.0f : -C_NEG);
            mx0 = fmaxf(mx0, fmaxf(S[nt][0], S[nt][1]));
            mx1 = fmaxf(mx1, fmaxf(S[nt][2], S[nt][3]));
        }
        #pragma unroll
        for (int o = 1; o <= 2; o <<= 1) {
            mx0 = fmaxf(mx0, __shfl_xor_sync(0xffffffffu, mx0, o));
            mx1 = fmaxf(mx1, __shfl_xor_sync(0xffffffffu, mx1, o));
        }
        float mn0 = fmaxf(m0, mx0), mn1 = fmaxf(m1, mx1);
        float cr0 = ex2f(m0 - mn0), cr1 = ex2f(m1 - mn1);
        m0 = mn0; m1 = mn1;

        // ---- exp2, row sums; pack P into A-fragments ----
        uint32_t ph0[8], ph1[8];
        float s0 = 0.0f, s1 = 0.0f;
        #pragma unroll
        for (int nt = 0; nt < 8; nt++) {
            float p0 = ex2f(S[nt][0] - mn0);
            float p1 = ex2f(S[nt][1] - mn0);
            float p2 = ex2f(S[nt][2] - mn1);
            float p3 = ex2f(S[nt][3] - mn1);
            s0 += p0 + p1; s1 += p2 + p3;
            ph0[nt] = f22h2(p0, p1);
            ph1[nt] = f22h2(p2, p3);
        }
        #pragma unroll
        for (int o = 1; o <= 2; o <<= 1) {
            s0 += __shfl_xor_sync(0xffffffffu, s0, o);
            s1 += __shfl_xor_sync(0xffffffffu, s1, o);
        }
        l0 = l0*cr0 + s0;
        l1 = l1*cr1 + s1;

        #pragma unroll
        for (int nt = 0; nt < 8; nt++) {
            O[nt][0] *= cr0; O[nt][1] *= cr0;
            O[nt][2] *= cr1; O[nt][3] *= cr1;
        }

        // ---- O += P @ V (V via ldmatrix.trans) ----
        #pragma unroll
        for (int ks = 0; ks < 4; ks++) {
            const uint32_t kvo = (uint32_t)ks * 2304u;   // 16 rows * 144B
            uint32_t a0 = ph0[2*ks];
            uint32_t a1 = ph1[2*ks];
            uint32_t a2 = ph0[2*ks+1];
            uint32_t a3 = ph1[2*ks+1];
            #pragma unroll
            for (int p = 0; p < 4; p++) {
                uint32_t b4[4];
                LDSM4T(b4, aV[p] + so2 + kvo);
                mma_f16(O[p*2  ], a0, a1, a2, a3, b4[0], b4[1]);
                mma_f16(O[p*2+1], a0, a1, a2, a3, b4[2], b4[3]);
            }
        }
        __syncthreads();
    }

    // ---- epilogue ----
    const int bb = bh >> 4, hh = bh & 15;
    const float inv0 = 1.0f / l0, inv1 = 1.0f / l1;
    const int l_0 = q0 + qr + gy, l_1 = l_0 + 8;
    float* o0 = &out[((size_t)bb*L + l_0)*DIMM + hh*DH];
    float* o1 = &out[((size_t)bb*L + l_1)*DIMM + hh*DH];
    #pragma unroll
    for (int nt = 0; nt < 8; nt++) {
        *(float2*)&o0[nt*8 + 2*gx] = make_float2(O[nt][0]*inv0, O[nt][1]*inv0);
        *(float2*)&o1[nt*8 + 2*gx] = make_float2(O[nt][2]*inv1, O[nt][3]*inv1);
    }
}

// ---------------- launch ----------------
extern "C" void kernel_launch(void* const* d_in, const int* in_sizes, int n_in,
                              void* d_out, int out_size) {
    const float* X  = (const float*)d_in[0];
    const float* Wq = (const float*)d_in[1];
    const float* bq = (const float*)d_in[2];
    const float* Wv = (const float*)d_in[3];
    const float* bv = (const float*)d_in[4];
    const float* ha = (const float*)d_in[5];
    float* out = (float*)d_out;

    cudaFuncSetAttribute(proj_h_kernel, cudaFuncAttributeMaxDynamicSharedMemorySize, PROJ_SM_BYTES);
    cudaFuncSetAttribute(attn_kernel,   cudaFuncAttributeMaxDynamicSharedMemorySize, ASM_BYTES);

    __half *xh, *xl, *wqh, *wql, *wvh;
    cudaGetSymbolAddress((void**)&xh,  g_XH);
    cudaGetSymbolAddress((void**)&xl,  g_XL);
    cudaGetSymbolAddress((void**)&wqh, g_WqH);
    cudaGetSymbolAddress((void**)&wql, g_WqL);
    cudaGetSymbolAddress((void**)&wvh, g_WvH);
    cvt_kernel<<<(TOK*DIMM/4)/256, 256>>>(X,  xh,  xl,  TOK*DIMM/4, 1);
    cvt_kernel<<<(DIMM*DIMM/4)/256, 256>>>(Wq, wqh, wql, DIMM*DIMM/4, 1);
    cvt_kernel<<<(DIMM*DIMM/4)/256, 256>>>(Wv, wvh, wvh, DIMM*DIMM/4, 0);

    dim3 pg(DIMM/64, TOK/128, 2);
    proj_h_kernel<<<pg, 256, PROJ_SM_BYTES>>>(bq, bv, ha);

    hash2_kernel<<<(BH*L)/256, 256>>>(ha);

    dim3 ag(L/128, BH);
    attn_kernel<<<ag, 256, ASM_BYTES>>>(out);
}

// round 17
// speedup vs baseline: 1.4267x; 1.0303x over previous
#include <cuda_runtime.h>
#include <cuda_fp16.h>
#include <math.h>
#include <stdint.h>

#define B 2
#define L 2048
#define DIMM 1024
#define H 16
#define DH 64
#define BH (B*H)      // 32
#define TOK (B*L)     // 4096

// ---------------- scratch ----------------
__device__ __half g_qkh[BH*L*DH];
__device__ __half g_vh [BH*L*DH];
__device__ float g_dot[BH*L];
__device__ float g_norm2[BH*L];
__device__ unsigned int g_maxn2[BH];
__device__ unsigned char g_hq[BH*L];
__device__ unsigned char g_hk[BH*L];
__device__ __half g_XH [TOK*DIMM];
__device__ __half g_XL [TOK*DIMM];
__device__ __half g_WqH[DIMM*DIMM];
__device__ __half g_WqL[DIMM*DIMM];
__device__ __half g_WvH[DIMM*DIMM];

__device__ __forceinline__ uint32_t f22h2(float a, float b){
    __half2 h = __floats2half2_rn(a, b);
    return *(uint32_t*)&h;
}
__device__ __forceinline__ float ex2f(float x){
    float r; asm("ex2.approx.f32 %0, %1;" : "=f"(r) : "f"(x)); return r;
}
__device__ __forceinline__ void mma_f16(float c[4],
    uint32_t a0, uint32_t a1, uint32_t a2, uint32_t a3,
    uint32_t b0, uint32_t b1)
{
    asm("mma.sync.aligned.m16n8k16.row.col.f32.f16.f16.f32 "
        "{%0,%1,%2,%3}, {%4,%5,%6,%7}, {%8,%9}, {%0,%1,%2,%3};"
        : "+f"(c[0]), "+f"(c[1]), "+f"(c[2]), "+f"(c[3])
        : "r"(a0), "r"(a1), "r"(a2), "r"(a3), "r"(b0), "r"(b1));
}
__device__ __forceinline__ uint32_t smem_u32(const void* p){
    uint32_t a;
    asm("{ .reg .u64 t; cvta.to.shared.u64 t, %1; cvt.u32.u64 %0, t; }" : "=r"(a) : "l"(p));
    return a;
}
#define CP16(dst, src) asm volatile("cp.async.ca.shared.global [%0], [%1], 16;" :: "r"(dst), "l"(src))
#define CP4(dst, src)  asm volatile("cp.async.ca.shared.global [%0], [%1], 4;"  :: "r"(dst), "l"(src))
#define CP_COMMIT()    asm volatile("cp.async.commit_group;" ::: "memory")
#define CP_WAIT1()     asm volatile("cp.async.wait_group 1;" ::: "memory")
#define LDSM4(r, addr) \
    asm volatile("ldmatrix.sync.aligned.m8n8.x4.shared.b16 {%0,%1,%2,%3}, [%4];" \
        : "=r"((r)[0]), "=r"((r)[1]), "=r"((r)[2]), "=r"((r)[3]) : "r"(addr))
#define LDSM4T(r, addr) \
    asm volatile("ldmatrix.sync.aligned.m8n8.x4.trans.shared.b16 {%0,%1,%2,%3}, [%4];" \
        : "=r"((r)[0]), "=r"((r)[1]), "=r"((r)[2]), "=r"((r)[3]) : "r"(addr))

// ============ split conversion ============
__global__ __launch_bounds__(256)
void cvt_kernel(const float* __restrict__ src, __half* __restrict__ dh,
                __half* __restrict__ dl, int n4, int makeLo)
{
    int i = blockIdx.x*blockDim.x + threadIdx.x;
    if (blockIdx.x == 0 && threadIdx.x < BH) g_maxn2[threadIdx.x] = 0u;
    if (i >= n4) return;
    float4 v = ((const float4*)src)[i];
    __half2 h0 = __floats2half2_rn(v.x, v.y);
    __half2 h1 = __floats2half2_rn(v.z, v.w);
    ((__half2*)dh)[2*i]   = h0;
    ((__half2*)dh)[2*i+1] = h1;
    if (makeLo) {
        __half2 l0 = __floats2half2_rn((v.x - __low2float(h0))*2048.0f,
                                       (v.y - __high2float(h0))*2048.0f);
        __half2 l1 = __floats2half2_rn((v.z - __low2float(h1))*2048.0f,
                                       (v.w - __high2float(h1))*2048.0f);
        ((__half2*)dl)[2*i]   = l0;
        ((__half2*)dl)[2*i+1] = l1;
    }
}

// ============ fp16 projection: 3-stage cp.async + ldmatrix, 8 warps 4x2 ============
#define HP2 40
#define ST_HALVES 15360
#define ST_BYTES  30720
#define XH_O 0
#define XL_O 10240
#define WH_O 20480
#define WL_O 25600
#define PROJ_SM_BYTES (3*ST_BYTES)    // 92160

__global__ __launch_bounds__(256, 2)
void proj_h_kernel(const float* __restrict__ bq,
                   const float* __restrict__ bv,
                   const float* __restrict__ ha)
{
    extern __shared__ __half hsm[];
    const uint32_t sb = smem_u32(hsm);

    const bool SPLIT = (blockIdx.z == 0);
    __half* out = SPLIT ? g_qkh : g_vh;
    const __half* WHg = SPLIT ? g_WqH : g_WvH;
    const float* bias = SPLIT ? bq : bv;

    const int m0 = blockIdx.y * 128;
    const int n0 = blockIdx.x * 64;
    const int tid = threadIdx.x;
    const int warp = tid >> 5;
    const int lane = tid & 31;
    const int gy = lane >> 2;
    const int gx = lane & 3;
    const int wm = warp >> 1;
    const int wn = warp & 1;
    const int qr = wm * 32;
    const int nb = wn * 32;

    const int xr = tid >> 1, xc = (tid & 1) * 16;
    const int wr = tid >> 2, wc = (tid & 3) * 8;

    const __half* xhp = &g_XH[(size_t)(m0+xr)*DIMM + xc];
    const __half* xlp = &g_XL[(size_t)(m0+xr)*DIMM + xc];
    const __half* whp = &WHg  [(size_t)(n0+wr)*DIMM + wc];
    const __half* wlp = &g_WqL[(size_t)(n0+wr)*DIMM + wc];

    const uint32_t dXH = sb + XH_O + ((uint32_t)xr*HP2 + xc)*2u;
    const uint32_t dXL = sb + XL_O + ((uint32_t)xr*HP2 + xc)*2u;
    const uint32_t dWH = sb + WH_O + ((uint32_t)wr*HP2 + wc)*2u;
    const uint32_t dWL = sb + WL_O + ((uint32_t)wr*HP2 + wc)*2u;

    const int lrow = lane & 7, lmat = lane >> 3;
    const uint32_t a_off = (((uint32_t)(qr + (lmat & 1)*8 + lrow))*HP2 + (lmat >> 1)*8)*2u;
    const uint32_t aXH = sb + XH_O + a_off;
    const uint32_t aXL = sb + XL_O + a_off;
    uint32_t aWH[2], aWL[2];
    #pragma unroll
    for (int p = 0; p < 2; p++) {
        uint32_t b_off = (((uint32_t)(nb + (p*2 + (lmat >> 1))*8 + lrow))*HP2 + (lmat & 1)*8)*2u;
        aWH[p] = sb + WH_O + b_off;
        aWL[p] = sb + WL_O + b_off;
    }

    float acc1[2][4][4];
    float acc2[2][4][4];
    #pragma unroll
    for (int t=0;t<2;t++)
        #pragma unroll
        for (int nt=0;nt<4;nt++)
            #pragma unroll
            for (int c=0;c<4;c++){ acc1[t][nt][c] = 0.0f; acc2[t][nt][c] = 0.0f; }

    // prologue: fill chunks 0,1 into stages 0,1
    #pragma unroll
    for (int pc = 0; pc < 2; pc++) {
        const int kk = pc * 32;
        const uint32_t so = (uint32_t)pc * ST_BYTES;
        CP16(dXH + so,      xhp + kk);
        CP16(dXH + so + 16, xhp + kk + 8);
        CP16(dWH + so,      whp + kk);
        if (SPLIT) {
            CP16(dXL + so,      xlp + kk);
            CP16(dXL + so + 16, xlp + kk + 8);
            CP16(dWL + so,      wlp + kk);
        }
        CP_COMMIT();
    }

    int stage = 0;
    for (int c = 0; c < 32; c++) {
        CP_WAIT1();           // fill(c) complete (only fill(c+1) may be pending)
        __syncthreads();

        const uint32_t so2 = (uint32_t)stage * ST_BYTES;

        #pragma unroll
        for (int ks = 0; ks < 2; ks++) {
            const uint32_t ko = (uint32_t)ks * 32u;
            uint32_t ah[2][4], al[2][4];
            #pragma unroll
            for (int t = 0; t < 2; t++) {
                LDSM4(ah[t], aXH + so2 + (uint32_t)t*1280u + ko);
                if (SPLIT) LDSM4(al[t], aXL + so2 + (uint32_t)t*1280u + ko);
            }
            #pragma unroll
            for (int p = 0; p < 2; p++) {
                uint32_t bh4[4], bl4[4];
                LDSM4(bh4, aWH[p] + so2 + ko);
                if (SPLIT) LDSM4(bl4, aWL[p] + so2 + ko);
                #pragma unroll
                for (int q = 0; q < 2; q++) {
                    const int nt = p*2 + q;
                    uint32_t bh0 = bh4[q*2], bh1 = bh4[q*2+1];
                    #pragma unroll
                    for (int t = 0; t < 2; t++) {
                        mma_f16(acc1[t][nt], ah[t][0], ah[t][1], ah[t][2], ah[t][3], bh0, bh1);
                        if (SPLIT) {
                            mma_f16(acc2[t][nt], ah[t][0], ah[t][1], ah[t][2], ah[t][3], bl4[q*2], bl4[q*2+1]);
                            mma_f16(acc2[t][nt], al[t][0], al[t][1], al[t][2], al[t][3], bh0, bh1);
                        }
                    }
                }
            }
        }

        // issue fill(c+2) into stage (c+2)%3 — safe: sync above proved compute(c-1) done
        if (c < 30) {
            const int kk = (c + 2) * 32;
            int ns = stage + 2; if (ns >= 3) ns -= 3;
            const uint32_t so = (uint32_t)ns * ST_BYTES;
            CP16(dXH + so,      xhp + kk);
            CP16(dXH + so + 16, xhp + kk + 8);
            CP16(dWH + so,      whp + kk);
            if (SPLIT) {
                CP16(dXL + so,      xlp + kk);
                CP16(dXL + so + 16, xlp + kk + 8);
                CP16(dWL + so,      wlp + kk);
            }
        }
        CP_COMMIT();
        if (++stage == 3) stage = 0;
    }

    // ---- epilogue: bias, fp16 store, hash partials ----
    __syncthreads();
    const int hh = blockIdx.x;
    const float inv2048 = 1.0f/2048.0f;
    float* pd = (float*)hsm;
    float* pn = pd + 256;

    #pragma unroll
    for (int t = 0; t < 2; t++) {
        const int r_0 = qr + t*16 + gy;
        const int r_1 = r_0 + 8;
        const int m_0 = m0 + r_0, m_1 = m0 + r_1;
        const int b0_ = m_0 >> 11, l0_ = m_0 & (L-1);
        const int b1_ = m_1 >> 11, l1_ = m_1 & (L-1);
        __half* o0 = &out[(((size_t)(b0_*H + hh)*L + l0_)*DH)];
        __half* o1 = &out[(((size_t)(b1_*H + hh)*L + l1_)*DH)];

        float dot0 = 0.f, n20 = 0.f, dot1 = 0.f, n21 = 0.f;
        #pragma unroll
        for (int nt = 0; nt < 4; nt++) {
            int col = nb + nt*8 + 2*gx;
            float bs0 = bias[hh*64 + col];
            float bs1 = bias[hh*64 + col + 1];
            float v00, v01, v10, v11;
            if (SPLIT) {
                v00 = fmaf(acc2[t][nt][0], inv2048, acc1[t][nt][0]) + bs0;
                v01 = fmaf(acc2[t][nt][1], inv2048, acc1[t][nt][1]) + bs1;
                v10 = fmaf(acc2[t][nt][2], inv2048, acc1[t][nt][2]) + bs0;
                v11 = fmaf(acc2[t][nt][3], inv2048, acc1[t][nt][3]) + bs1;
            } else {
                v00 = acc1[t][nt][0] + bs0; v01 = acc1[t][nt][1] + bs1;
                v10 = acc1[t][nt][2] + bs0; v11 = acc1[t][nt][3] + bs1;
            }
            *(uint32_t*)&o0[col] = f22h2(v00, v01);
            *(uint32_t*)&o1[col] = f22h2(v10, v11);
            if (SPLIT) {
                float a0 = ha[col], a1 = ha[col + 1];
                dot0 = fmaf(v00, a0, fmaf(v01, a1, dot0));
                dot1 = fmaf(v10, a0, fmaf(v11, a1, dot1));
                n20  = fmaf(v00, v00, fmaf(v01, v01, n20));
                n21  = fmaf(v10, v10, fmaf(v11, v11, n21));
            }
        }
        if (SPLIT) {
            #pragma unroll
            for (int o = 1; o <= 2; o <<= 1) {
                dot0 += __shfl_xor_sync(0xffffffffu, dot0, o);
                dot1 += __shfl_xor_sync(0xffffffffu, dot1, o);
                n20  += __shfl_xor_sync(0xffffffffu, n20, o);
                n21  += __shfl_xor_sync(0xffffffffu, n21, o);
            }
            if (gx == 0) {
                pd[r_0*2 + wn] = dot0;  pn[r_0*2 + wn] = n20;
                pd[r_1*2 + wn] = dot1;  pn[r_1*2 + wn] = n21;
            }
        }
    }
    if (SPLIT) {
        __syncthreads();
        if (tid < 128) {
            int r = tid;
            float dot = pd[r*2] + pd[r*2+1];
            float n2  = pn[r*2] + pn[r*2+1];
            int m = m0 + r;
            int bb = m >> 11, ll = m & (L-1);
            size_t gw = (size_t)(bb*H + hh)*L + ll;
            g_dot[gw] = dot;
            g_norm2[gw] = n2;
            atomicMax(&g_maxn2[bb*H + hh], __float_as_uint(n2));
        }
    }
}

// ---------------- hash ----------------
__global__ void hash2_kernel(const float* __restrict__ ha) {
    int t = blockIdx.x * blockDim.x + threadIdx.x;
    if (t >= BH*L) return;
    float dot = g_dot[t], n2 = g_norm2[t];
    float maxn = sqrtf(__uint_as_float(g_maxn2[t >> 11]));
    float s = 0.75f / fmaxf(maxn, 1e-12f);
    float nk2 = s*s*n2;
    float hkval = s*dot + (0.5f - nk2)*ha[DH] + (0.5f - nk2*nk2)*ha[DH+1];
    g_hq[t] = (dot   >= 0.0f) ? 1 : 0;
    g_hk[t] = (hkval >= 0.0f) ? 1 : 0;
}

// ============ fp16 flash attention: 3-stage cp.async + ldmatrix ============
// smem (bytes): Q[128][72] @0 | K 3x[64][72] @18432 | V 3x[64][72] @46080 | hk 3x64 @73728
#define AQ_B 0
#define AK_B 18432
#define AV_B 46080
#define AHK_B 73728
#define AST_B 9216
#define ASM_BYTES (73728 + 192)

#define C_SCL 0.1803368801111713f
#define C_NEG 14426.950408889634f

__global__ __launch_bounds__(256, 2)
void attn_kernel(float* __restrict__ out) {
    extern __shared__ __half smh[];
    const uint32_t sb = smem_u32(smh);

    const int bh = blockIdx.y;
    const int q0 = blockIdx.x * 128;
    const int tid = threadIdx.x;
    const int warp = tid >> 5;
    const int lane = tid & 31;
    const int gy = lane >> 2;
    const int gx = lane & 3;
    const int qr = warp * 16;

    // ---- Q fill (once) ----
    {
        int r = tid >> 1, c0 = (tid & 1) * 32;
        const __half* qp = &g_qkh[((size_t)bh*L + q0 + r)*DH + c0];
        #pragma unroll
        for (int c8 = 0; c8 < 4; c8++)
            *(uint4*)&smh[r*72 + c0 + c8*8] = *(const uint4*)&qp[c8*8];
    }

    const int hq0 = g_hq[(size_t)bh*L + q0 + qr + gy];
    const int hq1 = g_hq[(size_t)bh*L + q0 + qr + gy + 8];

    const int fr0 = tid >> 3,        fo0 = (tid & 7) * 8;
    const int fr1 = (tid + 256) >> 3, fo1 = ((tid + 256) & 7) * 8;
    const __half* kbase = &g_qkh[(size_t)bh*L*DH];
    const __half* vbase = &g_vh [(size_t)bh*L*DH];
    const uint32_t dK0 = sb + AK_B + ((uint32_t)fr0*72 + fo0)*2u;
    const uint32_t dK1 = sb + AK_B + ((uint32_t)fr1*72 + fo1)*2u;
    const uint32_t dV0 = sb + AV_B + ((uint32_t)fr0*72 + fo0)*2u;
    const uint32_t dV1 = sb + AV_B + ((uint32_t)fr1*72 + fo1)*2u;

    const int lrow = lane & 7, lmat = lane >> 3;
    const uint32_t aQ = sb + AQ_B + (((uint32_t)(qr + (lmat & 1)*8 + lrow))*72u + (lmat >> 1)*8u)*2u;
    uint32_t aK[4], aV[4];
    #pragma unroll
    for (int p = 0; p < 4; p++) {
        aK[p] = sb + AK_B + (((uint32_t)((p*2 + (lmat >> 1))*8 + lrow))*72u + (lmat & 1)*8u)*2u;
        aV[p] = sb + AV_B + (((uint32_t)((lmat & 1)*8 + lrow))*72u + (uint32_t)(p*2 + (lmat >> 1))*8u)*2u;
    }

    float O[8][4];
    #pragma unroll
    for (int nt=0;nt<8;nt++)
        #pragma unroll
        for (int c=0;c<4;c++) O[nt][c] = 0.0f;
    float m0 = -INFINITY, m1 = -INFINITY, l0 = 0.0f, l1 = 0.0f;

    // prologue: fill tiles 0,1 into stages 0,1
    #pragma unroll
    for (int pt = 0; pt < 2; pt++) {
        const size_t kn = (size_t)pt * 64 * DH;
        const uint32_t so = (uint32_t)pt * AST_B;
        CP16(dK0 + so, kbase + kn + (size_t)fr0*DH + fo0);
        CP16(dK1 + so, kbase + kn + (size_t)fr1*DH + fo1);
        CP16(dV0 + so, vbase + kn + (size_t)fr0*DH + fo0);
        CP16(dV1 + so, vbase + kn + (size_t)fr1*DH + fo1);
        if (tid < 16) CP4(sb + AHK_B + pt*64 + tid*4, &g_hk[(size_t)bh*L + pt*64 + tid*4]);
        CP_COMMIT();
    }

    int stage = 0;
    for (int it = 0; it < 32; it++) {
        CP_WAIT1();
        __syncthreads();

        const uint32_t so2 = (uint32_t)stage * AST_B;
        const unsigned char* hks = (const unsigned char*)smh + AHK_B + stage*64;

        // ---- S = Q @ K^T ----
        float S[8][4];
        #pragma unroll
        for (int nt=0;nt<8;nt++)
            #pragma unroll
            for (int c=0;c<4;c++) S[nt][c] = 0.0f;

        #pragma unroll
        for (int ks = 0; ks < 4; ks++) {
            const uint32_t ko = (uint32_t)ks * 32u;
            uint32_t a4[4];
            LDSM4(a4, aQ + ko);
            #pragma unroll
            for (int p = 0; p < 4; p++) {
                uint32_t b4[4];
                LDSM4(b4, aK[p] + so2 + ko);
                mma_f16(S[p*2  ], a4[0], a4[1], a4[2], a4[3], b4[0], b4[1]);
                mma_f16(S[p*2+1], a4[0], a4[1], a4[2], a4[3], b4[2], b4[3]);
            }
        }

        // ---- mask + scale; row max ----
        float mx0 = -INFINITY, mx1 = -INFINITY;
        #pragma unroll
        for (int nt = 0; nt < 8; nt++) {
            int k0b = hks[nt*8 + 2*gx];
            int k1b = hks[nt*8 + 2*gx + 1];
            S[nt][0] = fmaf(S[nt][0], C_SCL, (hq0 == k0b) ? 0.0f : -C_NEG);
            S[nt][1] = fmaf(S[nt][1], C_SCL, (hq0 == k1b) ? 0.0f : -C_NEG);
            S[nt][2] = fmaf(S[nt][2], C_SCL, (hq1 == k0b) ? 0.0f : -C_NEG);
            S[nt][3] = fmaf(S[nt][3], C_SCL, (hq1 == k1b) ? 0.0f : -C_NEG);
            mx0 = fmaxf(mx0, fmaxf(S[nt][0], S[nt][1]));
            mx1 = fmaxf(mx1, fmaxf(S[nt][2], S[nt][3]));
        }
        #pragma unroll
        for (int o = 1; o <= 2; o <<= 1) {
            mx0 = fmaxf(mx0, __shfl_xor_sync(0xffffffffu, mx0, o));
            mx1 = fmaxf(mx1, __shfl_xor_sync(0xffffffffu, mx1, o));
        }
        float mn0 = fmaxf(m0, mx0), mn1 = fmaxf(m1, mx1);
        float cr0 = ex2f(m0 - mn0), cr1 = ex2f(m1 - mn1);
        m0 = mn0; m1 = mn1;

        // ---- exp2, row sums; P into A-fragments ----
        uint32_t ph0[8], ph1[8];
        float s0 = 0.0f, s1 = 0.0f;
        #pragma unroll
        for (int nt = 0; nt < 8; nt++) {
            float p0 = ex2f(S[nt][0] - mn0);
            float p1 = ex2f(S[nt][1] - mn0);
            float p2 = ex2f(S[nt][2] - mn1);
            float p3 = ex2f(S[nt][3] - mn1);
            s0 += p0 + p1; s1 += p2 + p3;
            ph0[nt] = f22h2(p0, p1);
            ph1[nt] = f22h2(p2, p3);
        }
        #pragma unroll
        for (int o = 1; o <= 2; o <<= 1) {
            s0 += __shfl_xor_sync(0xffffffffu, s0, o);
            s1 += __shfl_xor_sync(0xffffffffu, s1, o);
        }
        l0 = l0*cr0 + s0;
        l1 = l1*cr1 + s1;

        #pragma unroll
        for (int nt = 0; nt < 8; nt++) {
            O[nt][0] *= cr0; O[nt][1] *= cr0;
            O[nt][2] *= cr1; O[nt][3] *= cr1;
        }

        // ---- O += P @ V (V via ldmatrix.trans) ----
        #pragma unroll
        for (int ks = 0; ks < 4; ks++) {
            const uint32_t kvo = (uint32_t)ks * 2304u;
            uint32_t a0 = ph0[2*ks];
            uint32_t a1 = ph1[2*ks];
            uint32_t a2 = ph0[2*ks+1];
            uint32_t a3 = ph1[2*ks+1];
            #pragma unroll
            for (int p = 0; p < 4; p++) {
                uint32_t b4[4];
                LDSM4T(b4, aV[p] + so2 + kvo);
                mma_f16(O[p*2  ], a0, a1, a2, a3, b4[0], b4[1]);
                mma_f16(O[p*2+1], a0, a1, a2, a3, b4[2], b4[3]);
            }
        }

        // issue fill(it+2) into stage (it+2)%3
        if (it < 30) {
            const size_t kn = (size_t)(it + 2) * 64 * DH;
            int ns = stage + 2; if (ns >= 3) ns -= 3;
            const uint32_t so = (uint32_t)ns * AST_B;
            CP16(dK0 + so, kbase + kn + (size_t)fr0*DH + fo0);
            CP16(dK1 + so, kbase + kn + (size_t)fr1*DH + fo1);
            CP16(dV0 + so, vbase + kn + (size_t)fr0*DH + fo0);
            CP16(dV1 + so, vbase + kn + (size_t)fr1*DH + fo1);
            if (tid < 16) CP4(sb + AHK_B + ns*64 + tid*4,
                              &g_hk[(size_t)bh*L + (it+2)*64 + tid*4]);
        }
        CP_COMMIT();
        if (++stage == 3) stage = 0;
    }

    // ---- epilogue ----
    const int bb = bh >> 4, hh = bh & 15;
    const float inv0 = 1.0f / l0, inv1 = 1.0f / l1;
    const int l_0 = q0 + qr + gy, l_1 = l_0 + 8;
    float* o0 = &out[((size_t)bb*L + l_0)*DIMM + hh*DH];
    float* o1 = &out[((size_t)bb*L + l_1)*DIMM + hh*DH];
    #pragma unroll
    for (int nt = 0; nt < 8; nt++) {
        *(float2*)&o0[nt*8 + 2*gx] = make_float2(O[nt][0]*inv0, O[nt][1]*inv0);
        *(float2*)&o1[nt*8 + 2*gx] = make_float2(O[nt][2]*inv1, O[nt][3]*inv1);
    }
}

// ---------------- launch ----------------
extern "C" void kernel_launch(void* const* d_in, const int* in_sizes, int n_in,
                              void* d_out, int out_size) {
    const float* X  = (const float*)d_in[0];
    const float* Wq = (const float*)d_in[1];
    const float* bq = (const float*)d_in[2];
    const float* Wv = (const float*)d_in[3];
    const float* bv = (const float*)d_in[4];
    const float* ha = (const float*)d_in[5];
    float* out = (float*)d_out;

    cudaFuncSetAttribute(proj_h_kernel, cudaFuncAttributeMaxDynamicSharedMemorySize, PROJ_SM_BYTES);
    cudaFuncSetAttribute(attn_kernel,   cudaFuncAttributeMaxDynamicSharedMemorySize, ASM_BYTES);

    __half *xh, *xl, *wqh, *wql, *wvh;
    cudaGetSymbolAddress((void**)&xh,  g_XH);
    cudaGetSymbolAddress((void**)&xl,  g_XL);
    cudaGetSymbolAddress((void**)&wqh, g_WqH);
    cudaGetSymbolAddress((void**)&wql, g_WqL);
    cudaGetSymbolAddress((void**)&wvh, g_WvH);
    cvt_kernel<<<(TOK*DIMM/4)/256, 256>>>(X,  xh,  xl,  TOK*DIMM/4, 1);
    cvt_kernel<<<(DIMM*DIMM/4)/256, 256>>>(Wq, wqh, wql, DIMM*DIMM/4, 1);
    cvt_kernel<<<(DIMM*DIMM/4)/256, 256>>>(Wv, wvh, wvh, DIMM*DIMM/4, 0);

    dim3 pg(DIMM/64, TOK/128, 2);
    proj_h_kernel<<<pg, 256, PROJ_SM_BYTES>>>(bq, bv, ha);

    hash2_kernel<<<(BH*L)/256, 256>>>(ha);

    dim3 ag(L/128, BH);
    attn_kernel<<<ag, 256, ASM_BYTES>>>(out);
}